// round 1
// baseline (speedup 1.0000x reference)
#include <cuda_runtime.h>
#include <math.h>

#define NN   20000
#define EE   320000
#define CC   64
#define NBF  16
#define RCUT 5.0f
#define CSP  (RCUT/(NBF-1))   // rbf center spacing = 1/3
#define WIDTH (RCUT/NBF)      // 0.3125
#define PI_F 3.14159265358979f
#define FULLMASK 0xffffffffu

// ---------------- device scratch (static allocation; no cudaMalloc) --------
static __device__ int   g_cnt;
static __device__ int   g_ci[EE], g_cj[EE];
static __device__ float g_cd[EE], g_cfc[EE];
static __device__ float g_crh[EE*3];
static __device__ float g_crbf[EE*NBF];

static __device__ float g_h0a[NN*CC];     // h0 layer-0 input (embedding)
static __device__ float g_h0b[NN*CC];     // h0 layer-1 input
static __device__ float g_h0c[NN*CC];     // h0 final
static __device__ float g_s0[NN*CC], g_s1[NN*CC];   // pre-activations
static __device__ float g_h1b[NN*3*CC];   // h1 layer-1 input  [N][3][C]
static __device__ float g_M0[NN*CC];      // scatter scratch
static __device__ float g_M1[NN*3*CC];
static __device__ float g_ds[NN*CC];      // silu-backprop scratch / readout w
static __device__ float g_gM0[NN*CC];
static __device__ float g_gM1[NN*3*CC];
static __device__ float g_gA[NN*CC];      // grad wrt h0 final
static __device__ float g_gB[NN*CC];      // grad wrt h0_1
static __device__ float g_gh1[NN*3*CC];   // grad wrt h1_1

__device__ __forceinline__ float warpRed(float v){
#pragma unroll
    for(int o=16;o>0;o>>=1) v += __shfl_xor_sync(FULLMASK, v, o);
    return v;
}

// ---------------- geometry + active-edge compaction ------------------------
__global__ void geom_k(const float* __restrict__ coord,
                       const int* __restrict__ ei, const int* __restrict__ ej)
{
    int e = blockIdx.x*blockDim.x + threadIdx.x;
    if(e >= EE) return;
    int i = ei[e], j = ej[e];
    float dx = coord[j*3+0] - coord[i*3+0];
    float dy = coord[j*3+1] - coord[i*3+1];
    float dz = coord[j*3+2] - coord[i*3+2];
    float d  = sqrtf(dx*dx + dy*dy + dz*dz + 1e-12f);
    if(d < RCUT){
        int pos = atomicAdd(&g_cnt, 1);
        g_ci[pos] = i; g_cj[pos] = j;
        g_cd[pos] = d;
        g_cfc[pos] = 0.5f*(cosf(PI_F*d/RCUT) + 1.0f);
        float inv = 1.0f/d;
        g_crh[pos*3+0] = dx*inv;
        g_crh[pos*3+1] = dy*inv;
        g_crh[pos*3+2] = dz*inv;
#pragma unroll
        for(int b=0;b<NBF;b++){
            float z = (d - b*CSP)/WIDTH;
            g_crbf[pos*NBF+b] = expf(-z*z);
        }
    }
}

// ---------------- embedding gather -----------------------------------------
__global__ void embed_k(const float* __restrict__ emb, const int* __restrict__ z)
{
    int idx = blockIdx.x*blockDim.x + threadIdx.x;
    if(idx >= NN*CC) return;
    int n = idx >> 6, c = idx & 63;
    g_h0a[idx] = emb[z[n]*CC + c];
}

// ---------------- forward edge kernel (warp per edge) -----------------------
template<bool H1Z>
__global__ __launch_bounds__(256) void edge_fwd_k(
    const float* __restrict__ Wr_l, const float* __restrict__ br_l,
    const float* __restrict__ h0,   const float* __restrict__ h1)
{
    __shared__ float sWr[4*NBF*CC];
    __shared__ float sbr[4*CC];
    int tid = threadIdx.x;
    int cnt = g_cnt;
    if((int)(blockIdx.x*8) >= cnt) return;
    for(int k=tid;k<4096;k+=256) sWr[k] = Wr_l[k];
    sbr[tid] = br_l[tid];
    __syncthreads();
    int e = blockIdx.x*8 + (tid>>5);
    if(e >= cnt) return;
    int lane = tid & 31;
    int c0 = lane, c1 = lane + 32;
    int i = g_ci[e], j = g_cj[e];
    float fc = g_cfc[e];
    float r0 = g_crh[e*3+0], r1 = g_crh[e*3+1], r2 = g_crh[e*3+2];
    float rb = (lane < NBF) ? g_crbf[e*NBF+lane] : 0.f;

    float pre[4][2];
#pragma unroll
    for(int p=0;p<4;p++){ pre[p][0]=sbr[p*64+c0]; pre[p][1]=sbr[p*64+c1]; }
#pragma unroll
    for(int b=0;b<NBF;b++){
        float r = __shfl_sync(FULLMASK, rb, b);
#pragma unroll
        for(int p=0;p<4;p++){
            pre[p][0] = fmaf(r, sWr[(p*NBF+b)*64+c0], pre[p][0]);
            pre[p][1] = fmaf(r, sWr[(p*NBF+b)*64+c1], pre[p][1]);
        }
    }
    float h0j0 = h0[j*64+c0], h0j1 = h0[j*64+c1];
    float v[3][2]; float t0 = 0.f, t1 = 0.f;
    if(!H1Z){
#pragma unroll
        for(int x=0;x<3;x++){ v[x][0]=h1[(j*3+x)*64+c0]; v[x][1]=h1[(j*3+x)*64+c1]; }
        t0 = v[0][0]*r0 + v[1][0]*r1 + v[2][0]*r2;
        t1 = v[0][1]*r0 + v[1][1]*r1 + v[2][1]*r2;
    }
    atomicAdd(&g_M0[i*64+c0], fc*(pre[0][0]*h0j0 + pre[2][0]*t0));
    atomicAdd(&g_M0[i*64+c1], fc*(pre[0][1]*h0j1 + pre[2][1]*t1));
    float rh[3] = {r0,r1,r2};
#pragma unroll
    for(int x=0;x<3;x++){
        float a0 = fc*(pre[1][0]*h0j0*rh[x] + (H1Z?0.f:pre[3][0]*v[x][0]));
        float a1 = fc*(pre[1][1]*h0j1*rh[x] + (H1Z?0.f:pre[3][1]*v[x][1]));
        atomicAdd(&g_M1[(i*3+x)*64+c0], a0);
        atomicAdd(&g_M1[(i*3+x)*64+c1], a1);
    }
}

// ---------------- backward edge kernel --------------------------------------
// MODE 1: last layer (h1 present, gM1 == 0, scatter grads into gh0/gh1)
// MODE 0: first layer (h1 == 0, gM1 present, no input-grad scatter)
template<int MODE>
__global__ __launch_bounds__(256) void edge_bwd_k(
    const float* __restrict__ Wr_l, const float* __restrict__ br_l,
    const float* __restrict__ h0,   const float* __restrict__ h1,
    const float* __restrict__ gM0,  const float* __restrict__ gM1,
    float* __restrict__ gh0, float* __restrict__ gh1, float* __restrict__ F)
{
    __shared__ float sWr[4*NBF*CC];
    __shared__ float sbr[4*CC];
    int tid = threadIdx.x;
    int cnt = g_cnt;
    if((int)(blockIdx.x*8) >= cnt) return;
    for(int k=tid;k<4096;k+=256) sWr[k] = Wr_l[k];
    sbr[tid] = br_l[tid];
    __syncthreads();
    int e = blockIdx.x*8 + (tid>>5);
    if(e >= cnt) return;
    int lane = tid & 31;
    int c0 = lane, c1 = lane + 32;
    int i = g_ci[e], j = g_cj[e];
    float fc = g_cfc[e], d = g_cd[e];
    float rh[3] = {g_crh[e*3+0], g_crh[e*3+1], g_crh[e*3+2]};
    float rb = (lane < NBF) ? g_crbf[e*NBF+lane] : 0.f;
    float wb = 0.f;
    if(lane < NBF){
        float z = (d - lane*CSP)/WIDTH;
        wb = rb * (-2.0f*z/WIDTH);          // d rbf / dd
    }
    float pre[4][2], q[4][2];
#pragma unroll
    for(int p=0;p<4;p++){
        pre[p][0]=sbr[p*64+c0]; pre[p][1]=sbr[p*64+c1];
        q[p][0]=0.f; q[p][1]=0.f;
    }
#pragma unroll
    for(int b=0;b<NBF;b++){
        float r = __shfl_sync(FULLMASK, rb, b);
        float w = __shfl_sync(FULLMASK, wb, b);
#pragma unroll
        for(int p=0;p<4;p++){
            float W0 = sWr[(p*NBF+b)*64+c0];
            float W1 = sWr[(p*NBF+b)*64+c1];
            pre[p][0] = fmaf(r, W0, pre[p][0]);
            pre[p][1] = fmaf(r, W1, pre[p][1]);
            q[p][0]   = fmaf(w, W0, q[p][0]);
            q[p][1]   = fmaf(w, W1, q[p][1]);
        }
    }
    float gm0[2] = {gM0[i*64+c0], gM0[i*64+c1]};
    float h0j[2] = {h0[j*64+c0],  h0[j*64+c1]};

    float sfc = 0.f, sd = 0.f, gr0 = 0.f, gr1 = 0.f, gr2 = 0.f;

    if(MODE == 1){
        float v[3][2];
#pragma unroll
        for(int x=0;x<3;x++){ v[x][0]=h1[(j*3+x)*64+c0]; v[x][1]=h1[(j*3+x)*64+c1]; }
        float t[2];
        t[0] = v[0][0]*rh[0] + v[1][0]*rh[1] + v[2][0]*rh[2];
        t[1] = v[0][1]*rh[0] + v[1][1]*rh[1] + v[2][1]*rh[2];
#pragma unroll
        for(int k=0;k<2;k++){
            float gf0 = gm0[k]*h0j[k];
            float gf2 = gm0[k]*t[k];
            sfc += gf0*pre[0][k] + gf2*pre[2][k];
            sd  += gf0*q[0][k]   + gf2*q[2][k];
            float f2 = fc*pre[2][k]*gm0[k];
            gr0 += f2*v[0][k]; gr1 += f2*v[1][k]; gr2 += f2*v[2][k];
        }
        // scatter grads into layer-1 inputs
        atomicAdd(&gh0[j*64+c0], gm0[0]*fc*pre[0][0]);
        atomicAdd(&gh0[j*64+c1], gm0[1]*fc*pre[0][1]);
#pragma unroll
        for(int x=0;x<3;x++){
            atomicAdd(&gh1[(j*3+x)*64+c0], gm0[0]*fc*pre[2][0]*rh[x]);
            atomicAdd(&gh1[(j*3+x)*64+c1], gm0[1]*fc*pre[2][1]*rh[x]);
        }
    } else {
        float gm1[3][2];
#pragma unroll
        for(int x=0;x<3;x++){ gm1[x][0]=gM1[(i*3+x)*64+c0]; gm1[x][1]=gM1[(i*3+x)*64+c1]; }
        float gmr[2];
        gmr[0] = gm1[0][0]*rh[0] + gm1[1][0]*rh[1] + gm1[2][0]*rh[2];
        gmr[1] = gm1[0][1]*rh[0] + gm1[1][1]*rh[1] + gm1[2][1]*rh[2];
#pragma unroll
        for(int k=0;k<2;k++){
            float gf0 = gm0[k]*h0j[k];
            float gf1 = gmr[k]*h0j[k];
            sfc += gf0*pre[0][k] + gf1*pre[1][k];
            sd  += gf0*q[0][k]   + gf1*q[1][k];
            float f1 = fc*pre[1][k]*h0j[k];
            gr0 += gm1[0][k]*f1; gr1 += gm1[1][k]*f1; gr2 += gm1[2][k]*f1;
        }
    }
    sfc = warpRed(sfc);
    sd  = warpRed(sd);
    gr0 = warpRed(gr0);
    gr1 = warpRed(gr1);
    gr2 = warpRed(gr2);

    float dfc = -0.5f*(PI_F/RCUT)*sinf(PI_F*d/RCUT);
    float gd  = fc*sd + sfc*dfc;
    float gdr = gr0*rh[0] + gr1*rh[1] + gr2*rh[2];
    float invd = 1.0f/d;
    if(lane < 3){
        float gx = (lane==0) ? gr0 : ((lane==1) ? gr1 : gr2);
        float rx = rh[lane];
        float grij = (gx - gdr*rx)*invd + gd*rx;
        atomicAdd(&F[i*3+lane],  grij);   // forces = -dE/dc ; dE/dc_i = -g_rij
        atomicAdd(&F[j*3+lane], -grij);
    }
}

// ---------------- node GEMM: out = epilogue(A@W1 [+ B@W2] [+ bias]) --------
__global__ __launch_bounds__(256) void mm_fwd(
    const float* __restrict__ A, const float* __restrict__ W1,
    const float* __restrict__ B, const float* __restrict__ W2,
    const float* __restrict__ bias, const float* __restrict__ ro2,
    float* __restrict__ out, float* __restrict__ sOut, int rows)
{
    __shared__ float sW1[4096];
    __shared__ float sW2[4096];
    __shared__ float sA[4][64];
    __shared__ float sB[4][64];
    int tid = threadIdx.x;
    for(int k=tid;k<4096;k+=256){ sW1[k]=W1[k]; if(B) sW2[k]=W2[k]; }
    int c = tid & 63, ty = tid >> 6;
    int row = blockIdx.x*4 + ty;
    bool valid = row < rows;
    if(valid){
        sA[ty][c] = A[row*64+c];
        if(B) sB[ty][c] = B[row*64+c];
    }
    __syncthreads();
    if(!valid) return;
    float acc = bias ? bias[c] : 0.f;
#pragma unroll 16
    for(int dd=0;dd<64;dd++) acc = fmaf(sA[ty][dd], sW1[dd*64+c], acc);
    if(B){
        float acc2 = 0.f;
#pragma unroll 16
        for(int dd=0;dd<64;dd++) acc2 = fmaf(sB[ty][dd], sW2[dd*64+c], acc2);
        acc += acc2;
    }
    if(ro2){
        float sig = 1.f/(1.f + expf(-acc));
        out[row*64+c] = ro2[c]*sig*fmaf(acc, 1.f-sig, 1.f);   // Wro2*silu'(u)
    } else if(sOut){
        sOut[row*64+c] = acc;
        float sig = 1.f/(1.f + expf(-acc));
        out[row*64+c] = acc*sig;
    } else {
        out[row*64+c] = acc;
    }
}

// ---------------- node GEMM transposed: out_k = G @ Wk^T --------------------
__global__ __launch_bounds__(256) void mm_bwdT(
    const float* __restrict__ G, const float* __restrict__ W1,
    const float* __restrict__ W2, float* __restrict__ out1,
    float* __restrict__ out2, int rows)
{
    __shared__ float sW1[64*65];
    __shared__ float sW2[64*65];
    __shared__ float sG[4][64];
    int tid = threadIdx.x;
    for(int k=tid;k<4096;k+=256){
        int cc = k>>6, dd = k&63;
        sW1[cc*65+dd] = W1[k];
        if(out2) sW2[cc*65+dd] = W2[k];
    }
    int c = tid & 63, ty = tid >> 6;
    int row = blockIdx.x*4 + ty;
    bool valid = row < rows;
    if(valid) sG[ty][c] = G[row*64+c];
    __syncthreads();
    if(!valid) return;
    float a1 = 0.f, a2 = 0.f;
#pragma unroll 16
    for(int dd=0;dd<64;dd++){
        float g = sG[ty][dd];
        a1 = fmaf(g, sW1[c*65+dd], a1);
        if(out2) a2 = fmaf(g, sW2[c*65+dd], a2);
    }
    out1[row*64+c] = a1;
    if(out2) out2[row*64+c] = a2;
}

// ---------------- elementwise silu backward --------------------------------
__global__ void dsilu_k(const float* __restrict__ g, const float* __restrict__ s,
                        float* __restrict__ out, int n)
{
    int i = blockIdx.x*blockDim.x + threadIdx.x;
    if(i >= n) return;
    float x = s[i];
    float sig = 1.f/(1.f + expf(-x));
    out[i] = g[i]*sig*fmaf(x, 1.f-sig, 1.f);
}

// ---------------- host orchestration ---------------------------------------
extern "C" void kernel_launch(void* const* d_in, const int* in_sizes, int n_in,
                              void* d_out, int out_size)
{
    const float* coord  = (const float*)d_in[0];
    const float* emb    = (const float*)d_in[1];
    const float* Wr     = (const float*)d_in[2];   // [L,4,NB,C]
    const float* br     = (const float*)d_in[3];   // [L,4,C]
    const float* Wself0 = (const float*)d_in[4];   // [L,C,C]
    const float* Wmsg0  = (const float*)d_in[5];
    const float* b0     = (const float*)d_in[6];   // [L,C]
    const float* Wmsg1  = (const float*)d_in[7];
    const float* Wself1 = (const float*)d_in[8];   // unused in grads path beyond fwd (h1_2 dead)
    const float* Wro1   = (const float*)d_in[9];
    const float* bro1   = (const float*)d_in[10];
    const float* Wro2   = (const float*)d_in[11];
    const int*   z      = (const int*)d_in[13];
    const int*   ei     = (const int*)d_in[14];
    const int*   ej     = (const int*)d_in[15];
    float* F = (float*)d_out;
    (void)Wself1; (void)in_sizes; (void)n_in; (void)out_size;

    void *pcnt, *pM0, *pM1, *pgh1;
    float *h0a,*h0b,*h0c,*s0,*s1,*h1b,*M0,*M1,*ds,*gM0p,*gM1p,*gA,*gB,*gh1;
    cudaGetSymbolAddress(&pcnt, g_cnt);
    cudaGetSymbolAddress((void**)&h0a, g_h0a);
    cudaGetSymbolAddress((void**)&h0b, g_h0b);
    cudaGetSymbolAddress((void**)&h0c, g_h0c);
    cudaGetSymbolAddress((void**)&s0,  g_s0);
    cudaGetSymbolAddress((void**)&s1,  g_s1);
    cudaGetSymbolAddress((void**)&h1b, g_h1b);
    cudaGetSymbolAddress((void**)&M0,  g_M0);
    cudaGetSymbolAddress((void**)&M1,  g_M1);
    cudaGetSymbolAddress((void**)&ds,  g_ds);
    cudaGetSymbolAddress((void**)&gM0p,g_gM0);
    cudaGetSymbolAddress((void**)&gM1p,g_gM1);
    cudaGetSymbolAddress((void**)&gA,  g_gA);
    cudaGetSymbolAddress((void**)&gB,  g_gB);
    cudaGetSymbolAddress((void**)&gh1, g_gh1);
    pM0 = M0; pM1 = M1; pgh1 = gh1;

    const int EB  = (EE + 7)/8;        // blocks for edge kernels (8 warps/block)
    const int NCB = (NN*CC + 255)/256;
    const int NRB = (NN + 3)/4;
    const int N3RB= (3*NN + 3)/4;

    cudaMemsetAsync(pcnt, 0, sizeof(int));
    cudaMemsetAsync(F, 0, NN*3*sizeof(float));
    geom_k<<<(EE+255)/256, 256>>>(coord, ei, ej);
    embed_k<<<NCB, 256>>>(emb, z);

    // ---- layer 0 forward
    cudaMemsetAsync(pM0, 0, NN*CC*sizeof(float));
    cudaMemsetAsync(pM1, 0, NN*3*CC*sizeof(float));
    edge_fwd_k<true><<<EB, 256>>>(Wr, br, h0a, nullptr);
    mm_fwd<<<NRB, 256>>>(M0, Wmsg0, h0a, Wself0, b0, nullptr, h0b, s0, NN);
    mm_fwd<<<N3RB, 256>>>(M1, Wmsg1, nullptr, nullptr, nullptr, nullptr, h1b, nullptr, 3*NN);

    // ---- layer 1 forward (h1 output is dead: skip it)
    cudaMemsetAsync(pM0, 0, NN*CC*sizeof(float));
    cudaMemsetAsync(pM1, 0, NN*3*CC*sizeof(float));
    edge_fwd_k<false><<<EB, 256>>>(Wr + 4096, br + 256, h0b, h1b);
    mm_fwd<<<NRB, 256>>>(M0, Wmsg0 + 4096, h0b, Wself0 + 4096, b0 + 64, nullptr, h0c, s1, NN);

    // ---- readout backward: gA = (Wro2 * silu'(h0c@Wro1+bro1)) @ Wro1^T
    mm_fwd<<<NRB, 256>>>(h0c, Wro1, nullptr, nullptr, bro1, Wro2, ds, nullptr, NN);
    mm_bwdT<<<NRB, 256>>>(ds, Wro1, nullptr, gA, nullptr, NN);

    // ---- layer 1 backward
    dsilu_k<<<NCB, 256>>>(gA, s1, ds, NN*CC);
    mm_bwdT<<<NRB, 256>>>(ds, Wmsg0 + 4096, Wself0 + 4096, gM0p, gB, NN);
    cudaMemsetAsync(pgh1, 0, NN*3*CC*sizeof(float));
    edge_bwd_k<1><<<EB, 256>>>(Wr + 4096, br + 256, h0b, h1b,
                               gM0p, nullptr, gB, gh1, F);

    // ---- layer 0 backward
    dsilu_k<<<NCB, 256>>>(gB, s0, ds, NN*CC);
    mm_bwdT<<<NRB, 256>>>(ds, Wmsg0, nullptr, gM0p, nullptr, NN);
    mm_bwdT<<<N3RB, 256>>>(gh1, Wmsg1, nullptr, gM1p, nullptr, 3*NN);
    edge_bwd_k<0><<<EB, 256>>>(Wr, br, h0a, nullptr,
                               gM0p, gM1p, nullptr, nullptr, F);
}

// round 2
// speedup vs baseline: 1.7924x; 1.7924x over previous
#include <cuda_runtime.h>
#include <math.h>

#define NN   20000
#define EE   320000
#define CC   64
#define NBF  16
#define RCUT 5.0f
#define CSP  (RCUT/(NBF-1))
#define WIDTH (RCUT/NBF)
#define PI_F 3.14159265358979f
#define FULLMASK 0xffffffffu

// ---------------- device scratch ------------------------------------------
static __device__ int   g_cnt;
static __device__ int   g_hist[NN];
static __device__ int   g_cur[NN];
static __device__ int   g_ci[EE], g_cj[EE];
static __device__ float g_cd[EE], g_cfc[EE];
static __device__ float g_crh[EE*3];
static __device__ float g_crbf[EE*NBF];

static __device__ float g_h0a[NN*CC];
static __device__ float g_h0b[NN*CC];
static __device__ float g_h0c[NN*CC];
static __device__ float g_s0[NN*CC], g_s1[NN*CC];
static __device__ float g_h1b[NN*3*CC];
static __device__ float g_M0[NN*CC];
static __device__ float g_M1[NN*3*CC];
static __device__ float g_gM0[NN*CC];
static __device__ float g_gM1[NN*3*CC];
static __device__ float g_gA[NN*CC];
static __device__ float g_gB[NN*CC];
static __device__ float g_gh1[NN*3*CC];

__device__ __forceinline__ float warpRed(float v){
#pragma unroll
    for(int o=16;o>0;o>>=1) v += __shfl_xor_sync(FULLMASK, v, o);
    return v;
}

// ---------------- geometry pass 1: histogram of valid edges by i -----------
__global__ void geomA_k(const float* __restrict__ coord,
                        const int* __restrict__ ei, const int* __restrict__ ej)
{
    int e = blockIdx.x*blockDim.x + threadIdx.x;
    if(e >= EE) return;
    int i = ei[e], j = ej[e];
    float dx = coord[j*3+0] - coord[i*3+0];
    float dy = coord[j*3+1] - coord[i*3+1];
    float dz = coord[j*3+2] - coord[i*3+2];
    float d2 = dx*dx + dy*dy + dz*dz + 1e-12f;
    if(d2 < RCUT*RCUT) atomicAdd(&g_hist[i], 1);
}

// ---------------- exclusive scan of histogram (single block) ---------------
__global__ __launch_bounds__(1024) void scan_k()
{
    __shared__ int swarp[32];
    int t = threadIdx.x;
    int base = t*20;
    int local[20];
    int s = 0;
#pragma unroll
    for(int q=0;q<20;q++){
        int idx = base + q;
        int v = (idx < NN) ? g_hist[idx] : 0;
        local[q] = s; s += v;
    }
    int lane = t & 31, wid = t >> 5;
    int inc = s;
#pragma unroll
    for(int o=1;o<32;o<<=1){
        int n = __shfl_up_sync(FULLMASK, inc, o);
        if(lane >= o) inc += n;
    }
    if(lane == 31) swarp[wid] = inc;
    __syncthreads();
    if(wid == 0){
        int v = swarp[lane];
#pragma unroll
        for(int o=1;o<32;o<<=1){
            int n = __shfl_up_sync(FULLMASK, v, o);
            if(lane >= o) v += n;
        }
        swarp[lane] = v;
    }
    __syncthreads();
    int offset = inc - s + ((wid > 0) ? swarp[wid-1] : 0);
#pragma unroll
    for(int q=0;q<20;q++){
        int idx = base + q;
        if(idx < NN) g_cur[idx] = offset + local[q];
    }
    if(t == 1023) g_cnt = offset + s;
}

// ---------------- geometry pass 2: write edges sorted by i -----------------
__global__ void geomB_k(const float* __restrict__ coord,
                        const int* __restrict__ ei, const int* __restrict__ ej)
{
    int e = blockIdx.x*blockDim.x + threadIdx.x;
    if(e >= EE) return;
    int i = ei[e], j = ej[e];
    float dx = coord[j*3+0] - coord[i*3+0];
    float dy = coord[j*3+1] - coord[i*3+1];
    float dz = coord[j*3+2] - coord[i*3+2];
    float d2 = dx*dx + dy*dy + dz*dz + 1e-12f;
    if(d2 >= RCUT*RCUT) return;
    float d = sqrtf(d2);
    int pos = atomicAdd(&g_cur[i], 1);
    g_ci[pos] = i; g_cj[pos] = j;
    g_cd[pos] = d;
    g_cfc[pos] = 0.5f*(cosf(PI_F*d/RCUT) + 1.0f);
    float inv = 1.0f/d;
    g_crh[pos*3+0] = dx*inv;
    g_crh[pos*3+1] = dy*inv;
    g_crh[pos*3+2] = dz*inv;
#pragma unroll
    for(int b=0;b<NBF;b++){
        float z = (d - b*CSP)/WIDTH;
        g_crbf[pos*NBF+b] = expf(-z*z);
    }
}

// ---------------- embedding gather -----------------------------------------
__global__ void embed_k(const float* __restrict__ emb, const int* __restrict__ z)
{
    int idx = blockIdx.x*blockDim.x + threadIdx.x;
    if(idx >= NN*CC) return;
    int n = idx >> 6, c = idx & 63;
    g_h0a[idx] = emb[z[n]*CC + c];
}

// ---------------- forward edge kernel: 8 edges per warp, run accumulation --
template<bool H1Z>
__global__ __launch_bounds__(256) void edge_fwd_k(
    const float* __restrict__ Wr_l, const float* __restrict__ br_l,
    const float* __restrict__ h0,   const float* __restrict__ h1)
{
    __shared__ float sWr[4*NBF*CC];
    __shared__ float sbr[4*CC];
    int tid = threadIdx.x;
    int cnt = g_cnt;
    if((int)(blockIdx.x*64) >= cnt) return;
    for(int k=tid;k<4096;k+=256) sWr[k] = Wr_l[k];
    sbr[tid] = br_l[tid];
    __syncthreads();
    int e0 = (blockIdx.x*8 + (tid>>5))*8;
    if(e0 >= cnt) return;
    int lane = tid & 31;
    int c0 = lane, c1 = lane + 32;
    int eend = min(e0 + 8, cnt);

    float a0c[2] = {0.f,0.f};
    float a1c[3][2] = {{0,0},{0,0},{0,0}};
    int curi = g_ci[e0];

    for(int e=e0;e<eend;e++){
        int i = g_ci[e];
        if(i != curi){
            atomicAdd(&g_M0[curi*64+c0], a0c[0]);
            atomicAdd(&g_M0[curi*64+c1], a0c[1]);
#pragma unroll
            for(int x=0;x<3;x++){
                atomicAdd(&g_M1[(curi*3+x)*64+c0], a1c[x][0]);
                atomicAdd(&g_M1[(curi*3+x)*64+c1], a1c[x][1]);
            }
            a0c[0]=a0c[1]=0.f;
#pragma unroll
            for(int x=0;x<3;x++){a1c[x][0]=0.f;a1c[x][1]=0.f;}
            curi = i;
        }
        int j = g_cj[e];
        float fc = g_cfc[e];
        float rh[3] = {g_crh[e*3+0], g_crh[e*3+1], g_crh[e*3+2]};
        float rb = (lane < NBF) ? g_crbf[e*NBF+lane] : 0.f;

        constexpr int NP = H1Z ? 2 : 4;
        float pre[NP][2];
#pragma unroll
        for(int p=0;p<NP;p++){ pre[p][0]=sbr[p*64+c0]; pre[p][1]=sbr[p*64+c1]; }
#pragma unroll
        for(int b=0;b<NBF;b++){
            float r = __shfl_sync(FULLMASK, rb, b);
#pragma unroll
            for(int p=0;p<NP;p++){
                pre[p][0] = fmaf(r, sWr[(p*NBF+b)*64+c0], pre[p][0]);
                pre[p][1] = fmaf(r, sWr[(p*NBF+b)*64+c1], pre[p][1]);
            }
        }
        float h0j0 = h0[j*64+c0], h0j1 = h0[j*64+c1];
        if(H1Z){
            a0c[0] = fmaf(fc*pre[0][0], h0j0, a0c[0]);
            a0c[1] = fmaf(fc*pre[0][1], h0j1, a0c[1]);
#pragma unroll
            for(int x=0;x<3;x++){
                a1c[x][0] = fmaf(fc*pre[1][0]*h0j0, rh[x], a1c[x][0]);
                a1c[x][1] = fmaf(fc*pre[1][1]*h0j1, rh[x], a1c[x][1]);
            }
        } else {
            float v[3][2];
#pragma unroll
            for(int x=0;x<3;x++){ v[x][0]=h1[(j*3+x)*64+c0]; v[x][1]=h1[(j*3+x)*64+c1]; }
            float t0 = v[0][0]*rh[0] + v[1][0]*rh[1] + v[2][0]*rh[2];
            float t1 = v[0][1]*rh[0] + v[1][1]*rh[1] + v[2][1]*rh[2];
            a0c[0] += fc*(pre[0][0]*h0j0 + pre[2][0]*t0);
            a0c[1] += fc*(pre[0][1]*h0j1 + pre[2][1]*t1);
#pragma unroll
            for(int x=0;x<3;x++){
                a1c[x][0] += fc*(pre[1][0]*h0j0*rh[x] + pre[3][0]*v[x][0]);
                a1c[x][1] += fc*(pre[1][1]*h0j1*rh[x] + pre[3][1]*v[x][1]);
            }
        }
    }
    atomicAdd(&g_M0[curi*64+c0], a0c[0]);
    atomicAdd(&g_M0[curi*64+c1], a0c[1]);
#pragma unroll
    for(int x=0;x<3;x++){
        atomicAdd(&g_M1[(curi*3+x)*64+c0], a1c[x][0]);
        atomicAdd(&g_M1[(curi*3+x)*64+c1], a1c[x][1]);
    }
}

// ---------------- backward edge kernel: 8 edges/warp -----------------------
// MODE 1: layer-1 (h1 present, gM1==0, scatter into gh0/gh1); paths {0,2}
// MODE 0: layer-0 (h1==0, gM1 present);                        paths {0,1}
template<int MODE>
__global__ __launch_bounds__(256) void edge_bwd_k(
    const float* __restrict__ Wr_l, const float* __restrict__ br_l,
    const float* __restrict__ h0,   const float* __restrict__ h1,
    const float* __restrict__ gM0,  const float* __restrict__ gM1,
    float* __restrict__ gh0, float* __restrict__ gh1, float* __restrict__ F)
{
    __shared__ float sWr[4*NBF*CC];
    __shared__ float sbr[4*CC];
    int tid = threadIdx.x;
    int cnt = g_cnt;
    if((int)(blockIdx.x*64) >= cnt) return;
    for(int k=tid;k<4096;k+=256) sWr[k] = Wr_l[k];
    sbr[tid] = br_l[tid];
    __syncthreads();
    int e0 = (blockIdx.x*8 + (tid>>5))*8;
    if(e0 >= cnt) return;
    int lane = tid & 31;
    int c0 = lane, c1 = lane + 32;
    int eend = min(e0 + 8, cnt);
    constexpr int PB = (MODE==1) ? 2 : 1;

    int curi = g_ci[e0];
    float gm0[2], gm1[3][2];
    float fi = 0.f;   // lane<3: run-accumulated force on atom i
    {
        gm0[0] = gM0[curi*64+c0]; gm0[1] = gM0[curi*64+c1];
        if(MODE==0){
#pragma unroll
            for(int x=0;x<3;x++){ gm1[x][0]=gM1[(curi*3+x)*64+c0]; gm1[x][1]=gM1[(curi*3+x)*64+c1]; }
        }
    }

    for(int e=e0;e<eend;e++){
        int i = g_ci[e];
        if(i != curi){
            if(lane < 3) atomicAdd(&F[curi*3+lane], fi);
            fi = 0.f;
            curi = i;
            gm0[0] = gM0[curi*64+c0]; gm0[1] = gM0[curi*64+c1];
            if(MODE==0){
#pragma unroll
                for(int x=0;x<3;x++){ gm1[x][0]=gM1[(curi*3+x)*64+c0]; gm1[x][1]=gM1[(curi*3+x)*64+c1]; }
            }
        }
        int j = g_cj[e];
        float fc = g_cfc[e], d = g_cd[e];
        float rh[3] = {g_crh[e*3+0], g_crh[e*3+1], g_crh[e*3+2]};
        float rb = 0.f, wb = 0.f;
        if(lane < NBF){
            rb = g_crbf[e*NBF+lane];
            float z = (d - lane*CSP)/WIDTH;
            wb = rb * (-2.0f*z/WIDTH);
        }
        float preA[2], preB[2], qA[2]={0,0}, qB[2]={0,0};
        preA[0]=sbr[0*64+c0]; preA[1]=sbr[0*64+c1];
        preB[0]=sbr[PB*64+c0]; preB[1]=sbr[PB*64+c1];
#pragma unroll
        for(int b=0;b<NBF;b++){
            float r = __shfl_sync(FULLMASK, rb, b);
            float w = __shfl_sync(FULLMASK, wb, b);
            float WA0 = sWr[(0*NBF+b)*64+c0], WA1 = sWr[(0*NBF+b)*64+c1];
            float WB0 = sWr[(PB*NBF+b)*64+c0], WB1 = sWr[(PB*NBF+b)*64+c1];
            preA[0] = fmaf(r, WA0, preA[0]); preA[1] = fmaf(r, WA1, preA[1]);
            preB[0] = fmaf(r, WB0, preB[0]); preB[1] = fmaf(r, WB1, preB[1]);
            qA[0] = fmaf(w, WA0, qA[0]); qA[1] = fmaf(w, WA1, qA[1]);
            qB[0] = fmaf(w, WB0, qB[0]); qB[1] = fmaf(w, WB1, qB[1]);
        }
        float h0j[2] = {h0[j*64+c0], h0[j*64+c1]};
        float sfc=0.f, sd=0.f, gr0=0.f, gr1=0.f, gr2=0.f;

        if(MODE == 1){
            float v[3][2];
#pragma unroll
            for(int x=0;x<3;x++){ v[x][0]=h1[(j*3+x)*64+c0]; v[x][1]=h1[(j*3+x)*64+c1]; }
            float t[2];
            t[0] = v[0][0]*rh[0] + v[1][0]*rh[1] + v[2][0]*rh[2];
            t[1] = v[0][1]*rh[0] + v[1][1]*rh[1] + v[2][1]*rh[2];
#pragma unroll
            for(int k=0;k<2;k++){
                float gf0 = gm0[k]*h0j[k];
                float gf2 = gm0[k]*t[k];
                sfc += gf0*preA[k] + gf2*preB[k];
                sd  += gf0*qA[k]   + gf2*qB[k];
                float f2 = fc*preB[k]*gm0[k];
                gr0 += f2*v[0][k]; gr1 += f2*v[1][k]; gr2 += f2*v[2][k];
            }
            atomicAdd(&gh0[j*64+c0], gm0[0]*fc*preA[0]);
            atomicAdd(&gh0[j*64+c1], gm0[1]*fc*preA[1]);
#pragma unroll
            for(int x=0;x<3;x++){
                atomicAdd(&gh1[(j*3+x)*64+c0], gm0[0]*fc*preB[0]*rh[x]);
                atomicAdd(&gh1[(j*3+x)*64+c1], gm0[1]*fc*preB[1]*rh[x]);
            }
        } else {
            float gmr[2];
            gmr[0] = gm1[0][0]*rh[0] + gm1[1][0]*rh[1] + gm1[2][0]*rh[2];
            gmr[1] = gm1[0][1]*rh[0] + gm1[1][1]*rh[1] + gm1[2][1]*rh[2];
#pragma unroll
            for(int k=0;k<2;k++){
                float gf0 = gm0[k]*h0j[k];
                float gf1 = gmr[k]*h0j[k];
                sfc += gf0*preA[k] + gf1*preB[k];
                sd  += gf0*qA[k]   + gf1*qB[k];
                float f1 = fc*preB[k]*h0j[k];
                gr0 += gm1[0][k]*f1; gr1 += gm1[1][k]*f1; gr2 += gm1[2][k]*f1;
            }
        }
        sfc = warpRed(sfc);
        sd  = warpRed(sd);
        gr0 = warpRed(gr0);
        gr1 = warpRed(gr1);
        gr2 = warpRed(gr2);

        float dfc = -0.5f*(PI_F/RCUT)*sinf(PI_F*d/RCUT);
        float gd  = fc*sd + sfc*dfc;
        float gdr = gr0*rh[0] + gr1*rh[1] + gr2*rh[2];
        float invd = 1.0f/d;
        if(lane < 3){
            float gx = (lane==0) ? gr0 : ((lane==1) ? gr1 : gr2);
            float rx = rh[lane];
            float grij = (gx - gdr*rx)*invd + gd*rx;
            fi += grij;
            atomicAdd(&F[j*3+lane], -grij);
        }
    }
    if(lane < 3) atomicAdd(&F[curi*3+lane], fi);
}

// ---------------- node GEMM: out = epilogue(A@W1 [+ B@W2] [+ bias]) --------
// 64 rows/block, 256 threads, 4x4 register tile per thread.
__global__ __launch_bounds__(256) void mm_fwd(
    const float* __restrict__ A, const float* __restrict__ W1,
    const float* __restrict__ B, const float* __restrict__ W2,
    const float* __restrict__ bias, const float* __restrict__ ro2,
    float* __restrict__ out, float* __restrict__ sOut, int rows)
{
    __shared__ float sW[64*64];
    __shared__ float sX[64*65];
    int tid = threadIdx.x;
    int row0 = blockIdx.x*64;
    int tc = tid & 15, tr = tid >> 4;
    float acc[4][4];
    if(bias){
        float4 b = *(const float4*)&bias[4*tc];
#pragma unroll
        for(int i=0;i<4;i++){ acc[i][0]=b.x; acc[i][1]=b.y; acc[i][2]=b.z; acc[i][3]=b.w; }
    } else {
#pragma unroll
        for(int i=0;i<4;i++){ acc[i][0]=acc[i][1]=acc[i][2]=acc[i][3]=0.f; }
    }
    int nph = B ? 2 : 1;
    for(int ph=0; ph<nph; ph++){
        const float* Xp = ph ? B : A;
        const float* Wp = ph ? W2 : W1;
        if(ph) __syncthreads();
        for(int k=tid;k<4096;k+=256) sW[k] = Wp[k];
        for(int k=tid;k<4096;k+=256){
            int r = k>>6, c = k&63;
            int gr = row0 + r;
            sX[r*65+c] = (gr < rows) ? Xp[gr*64+c] : 0.f;
        }
        __syncthreads();
        const float* xr = &sX[(tr*4)*65];
#pragma unroll 8
        for(int k=0;k<64;k++){
            float a0 = xr[k], a1 = xr[65+k], a2 = xr[130+k], a3 = xr[195+k];
            float4 w = *(const float4*)&sW[k*64 + tc*4];
            acc[0][0]=fmaf(a0,w.x,acc[0][0]); acc[0][1]=fmaf(a0,w.y,acc[0][1]);
            acc[0][2]=fmaf(a0,w.z,acc[0][2]); acc[0][3]=fmaf(a0,w.w,acc[0][3]);
            acc[1][0]=fmaf(a1,w.x,acc[1][0]); acc[1][1]=fmaf(a1,w.y,acc[1][1]);
            acc[1][2]=fmaf(a1,w.z,acc[1][2]); acc[1][3]=fmaf(a1,w.w,acc[1][3]);
            acc[2][0]=fmaf(a2,w.x,acc[2][0]); acc[2][1]=fmaf(a2,w.y,acc[2][1]);
            acc[2][2]=fmaf(a2,w.z,acc[2][2]); acc[2][3]=fmaf(a2,w.w,acc[2][3]);
            acc[3][0]=fmaf(a3,w.x,acc[3][0]); acc[3][1]=fmaf(a3,w.y,acc[3][1]);
            acc[3][2]=fmaf(a3,w.z,acc[3][2]); acc[3][3]=fmaf(a3,w.w,acc[3][3]);
        }
    }
    float4 ro2v = make_float4(0,0,0,0);
    if(ro2) ro2v = *(const float4*)&ro2[4*tc];
#pragma unroll
    for(int i=0;i<4;i++){
        int r = row0 + tr*4 + i;
        if(r >= rows) continue;
        float4 o;
        float* oo = &o.x;
#pragma unroll
        for(int jj=0;jj<4;jj++){
            float u = acc[i][jj];
            float val;
            if(ro2){
                float sig = 1.f/(1.f + expf(-u));
                float rr = (&ro2v.x)[jj];
                val = rr*sig*fmaf(u, 1.f-sig, 1.f);
            } else if(sOut){
                float sig = 1.f/(1.f + expf(-u));
                val = u*sig;
            } else {
                val = u;
            }
            oo[jj] = val;
        }
        if(sOut){
            float4 so = make_float4(acc[i][0],acc[i][1],acc[i][2],acc[i][3]);
            *(float4*)&sOut[r*64 + tc*4] = so;
        }
        *(float4*)&out[r*64 + tc*4] = o;
    }
}

// ---------------- node GEMM transposed with fused dsilu --------------------
// out_k = ds @ Wk^T, ds = S ? G*silu'(S) : G
__global__ __launch_bounds__(256) void mm_bwdT(
    const float* __restrict__ G, const float* __restrict__ S,
    const float* __restrict__ W1, const float* __restrict__ W2,
    float* __restrict__ out1, float* __restrict__ out2, int rows)
{
    __shared__ float sWt[64*68];
    __shared__ float sG[64*65];
    int tid = threadIdx.x;
    int row0 = blockIdx.x*64;
    int tc = tid & 15, tr = tid >> 4;
    for(int k=tid;k<4096;k+=256){
        int r = k>>6, c = k&63;
        int gr = row0 + r;
        float v = 0.f;
        if(gr < rows){
            float g = G[gr*64+c];
            if(S){
                float x = S[gr*64+c];
                float sig = 1.f/(1.f + expf(-x));
                v = g*sig*fmaf(x, 1.f-sig, 1.f);
            } else v = g;
        }
        sG[r*65+c] = v;
    }
    int nph = out2 ? 2 : 1;
    for(int ph=0; ph<nph; ph++){
        const float* Wp = ph ? W2 : W1;
        float* op = ph ? out2 : out1;
        if(ph) __syncthreads();
        for(int k=tid;k<4096;k+=256){
            int cout = k>>6, dd = k&63;
            sWt[dd*68+cout] = Wp[k];
        }
        __syncthreads();
        float acc[4][4];
#pragma unroll
        for(int i=0;i<4;i++){ acc[i][0]=acc[i][1]=acc[i][2]=acc[i][3]=0.f; }
        const float* xr = &sG[(tr*4)*65];
#pragma unroll 8
        for(int k=0;k<64;k++){
            float a0 = xr[k], a1 = xr[65+k], a2 = xr[130+k], a3 = xr[195+k];
            float4 w = *(const float4*)&sWt[k*68 + tc*4];
            acc[0][0]=fmaf(a0,w.x,acc[0][0]); acc[0][1]=fmaf(a0,w.y,acc[0][1]);
            acc[0][2]=fmaf(a0,w.z,acc[0][2]); acc[0][3]=fmaf(a0,w.w,acc[0][3]);
            acc[1][0]=fmaf(a1,w.x,acc[1][0]); acc[1][1]=fmaf(a1,w.y,acc[1][1]);
            acc[1][2]=fmaf(a1,w.z,acc[1][2]); acc[1][3]=fmaf(a1,w.w,acc[1][3]);
            acc[2][0]=fmaf(a2,w.x,acc[2][0]); acc[2][1]=fmaf(a2,w.y,acc[2][1]);
            acc[2][2]=fmaf(a2,w.z,acc[2][2]); acc[2][3]=fmaf(a2,w.w,acc[2][3]);
            acc[3][0]=fmaf(a3,w.x,acc[3][0]); acc[3][1]=fmaf(a3,w.y,acc[3][1]);
            acc[3][2]=fmaf(a3,w.z,acc[3][2]); acc[3][3]=fmaf(a3,w.w,acc[3][3]);
        }
#pragma unroll
        for(int i=0;i<4;i++){
            int r = row0 + tr*4 + i;
            if(r >= rows) continue;
            float4 o = make_float4(acc[i][0],acc[i][1],acc[i][2],acc[i][3]);
            *(float4*)&op[r*64 + tc*4] = o;
        }
    }
}

// ---------------- fused readout backward -----------------------------------
// u = A@Wro1 + bro1; w = Wro2*silu'(u); gA = w@Wro1^T
__global__ __launch_bounds__(256) void readout_k(
    const float* __restrict__ A, const float* __restrict__ Wro1,
    const float* __restrict__ bro1, const float* __restrict__ Wro2,
    float* __restrict__ gA, int rows)
{
    __shared__ float sW[64*68];
    __shared__ float sX[64*65];
    int tid = threadIdx.x;
    int row0 = blockIdx.x*64;
    int tc = tid & 15, tr = tid >> 4;
    for(int k=tid;k<4096;k+=256) sW[k] = Wro1[k];
    for(int k=tid;k<4096;k+=256){
        int r = k>>6, c = k&63;
        int gr = row0 + r;
        sX[r*65+c] = (gr < rows) ? A[gr*64+c] : 0.f;
    }
    __syncthreads();
    float acc[4][4];
    {
        float4 b = *(const float4*)&bro1[4*tc];
#pragma unroll
        for(int i=0;i<4;i++){ acc[i][0]=b.x; acc[i][1]=b.y; acc[i][2]=b.z; acc[i][3]=b.w; }
    }
    {
        const float* xr = &sX[(tr*4)*65];
#pragma unroll 8
        for(int k=0;k<64;k++){
            float a0 = xr[k], a1 = xr[65+k], a2 = xr[130+k], a3 = xr[195+k];
            float4 w = *(const float4*)&sW[k*64 + tc*4];
            acc[0][0]=fmaf(a0,w.x,acc[0][0]); acc[0][1]=fmaf(a0,w.y,acc[0][1]);
            acc[0][2]=fmaf(a0,w.z,acc[0][2]); acc[0][3]=fmaf(a0,w.w,acc[0][3]);
            acc[1][0]=fmaf(a1,w.x,acc[1][0]); acc[1][1]=fmaf(a1,w.y,acc[1][1]);
            acc[1][2]=fmaf(a1,w.z,acc[1][2]); acc[1][3]=fmaf(a1,w.w,acc[1][3]);
            acc[2][0]=fmaf(a2,w.x,acc[2][0]); acc[2][1]=fmaf(a2,w.y,acc[2][1]);
            acc[2][2]=fmaf(a2,w.z,acc[2][2]); acc[2][3]=fmaf(a2,w.w,acc[2][3]);
            acc[3][0]=fmaf(a3,w.x,acc[3][0]); acc[3][1]=fmaf(a3,w.y,acc[3][1]);
            acc[3][2]=fmaf(a3,w.z,acc[3][2]); acc[3][3]=fmaf(a3,w.w,acc[3][3]);
        }
    }
    __syncthreads();   // done reading sW/sX
    {
        float4 ro2v = *(const float4*)&Wro2[4*tc];
#pragma unroll
        for(int i=0;i<4;i++){
#pragma unroll
            for(int jj=0;jj<4;jj++){
                float u = acc[i][jj];
                float sig = 1.f/(1.f + expf(-u));
                float w = (&ro2v.x)[jj]*sig*fmaf(u, 1.f-sig, 1.f);
                sX[(tr*4+i)*65 + tc*4 + jj] = w;
            }
        }
    }
    for(int k=tid;k<4096;k+=256){
        int cout = k>>6, dd = k&63;
        sW[dd*68+cout] = Wro1[k];   // transposed: sW[c][k_out]
    }
    __syncthreads();
    float acc2[4][4];
#pragma unroll
    for(int i=0;i<4;i++){ acc2[i][0]=acc2[i][1]=acc2[i][2]=acc2[i][3]=0.f; }
    {
        const float* xr = &sX[(tr*4)*65];
#pragma unroll 8
        for(int k=0;k<64;k++){
            float a0 = xr[k], a1 = xr[65+k], a2 = xr[130+k], a3 = xr[195+k];
            float4 w = *(const float4*)&sW[k*68 + tc*4];
            acc2[0][0]=fmaf(a0,w.x,acc2[0][0]); acc2[0][1]=fmaf(a0,w.y,acc2[0][1]);
            acc2[0][2]=fmaf(a0,w.z,acc2[0][2]); acc2[0][3]=fmaf(a0,w.w,acc2[0][3]);
            acc2[1][0]=fmaf(a1,w.x,acc2[1][0]); acc2[1][1]=fmaf(a1,w.y,acc2[1][1]);
            acc2[1][2]=fmaf(a1,w.z,acc2[1][2]); acc2[1][3]=fmaf(a1,w.w,acc2[1][3]);
            acc2[2][0]=fmaf(a2,w.x,acc2[2][0]); acc2[2][1]=fmaf(a2,w.y,acc2[2][1]);
            acc2[2][2]=fmaf(a2,w.z,acc2[2][2]); acc2[2][3]=fmaf(a2,w.w,acc2[2][3]);
            acc2[3][0]=fmaf(a3,w.x,acc2[3][0]); acc2[3][1]=fmaf(a3,w.y,acc2[3][1]);
            acc2[3][2]=fmaf(a3,w.z,acc2[3][2]); acc2[3][3]=fmaf(a3,w.w,acc2[3][3]);
        }
    }
#pragma unroll
    for(int i=0;i<4;i++){
        int r = row0 + tr*4 + i;
        if(r >= rows) continue;
        float4 o = make_float4(acc2[i][0],acc2[i][1],acc2[i][2],acc2[i][3]);
        *(float4*)&gA[r*64 + tc*4] = o;
    }
}

// ---------------- host orchestration ---------------------------------------
extern "C" void kernel_launch(void* const* d_in, const int* in_sizes, int n_in,
                              void* d_out, int out_size)
{
    const float* coord  = (const float*)d_in[0];
    const float* emb    = (const float*)d_in[1];
    const float* Wr     = (const float*)d_in[2];
    const float* br     = (const float*)d_in[3];
    const float* Wself0 = (const float*)d_in[4];
    const float* Wmsg0  = (const float*)d_in[5];
    const float* b0     = (const float*)d_in[6];
    const float* Wmsg1  = (const float*)d_in[7];
    const float* Wro1   = (const float*)d_in[9];
    const float* bro1   = (const float*)d_in[10];
    const float* Wro2   = (const float*)d_in[11];
    const int*   z      = (const int*)d_in[13];
    const int*   ei     = (const int*)d_in[14];
    const int*   ej     = (const int*)d_in[15];
    float* F = (float*)d_out;
    (void)in_sizes; (void)n_in; (void)out_size;

    void *phist;
    float *h0a,*h0b,*h0c,*s0,*s1,*h1b,*M0,*M1,*gM0p,*gM1p,*gA,*gB,*gh1;
    cudaGetSymbolAddress(&phist, g_hist);
    cudaGetSymbolAddress((void**)&h0a, g_h0a);
    cudaGetSymbolAddress((void**)&h0b, g_h0b);
    cudaGetSymbolAddress((void**)&h0c, g_h0c);
    cudaGetSymbolAddress((void**)&s0,  g_s0);
    cudaGetSymbolAddress((void**)&s1,  g_s1);
    cudaGetSymbolAddress((void**)&h1b, g_h1b);
    cudaGetSymbolAddress((void**)&M0,  g_M0);
    cudaGetSymbolAddress((void**)&M1,  g_M1);
    cudaGetSymbolAddress((void**)&gM0p,g_gM0);
    cudaGetSymbolAddress((void**)&gM1p,g_gM1);
    cudaGetSymbolAddress((void**)&gA,  g_gA);
    cudaGetSymbolAddress((void**)&gB,  g_gB);
    cudaGetSymbolAddress((void**)&gh1, g_gh1);

    const int EB  = (EE + 63)/64;      // 8 warps x 8 edges per block
    const int NCB = (NN*CC + 255)/256;
    const int G1  = (NN + 63)/64;
    const int G3  = (3*NN + 63)/64;

    cudaMemsetAsync(phist, 0, NN*sizeof(int));
    cudaMemsetAsync(F, 0, NN*3*sizeof(float));
    geomA_k<<<(EE+255)/256, 256>>>(coord, ei, ej);
    scan_k<<<1, 1024>>>();
    geomB_k<<<(EE+255)/256, 256>>>(coord, ei, ej);
    embed_k<<<NCB, 256>>>(emb, z);

    // ---- layer 0 forward
    cudaMemsetAsync(M0, 0, NN*CC*sizeof(float));
    cudaMemsetAsync(M1, 0, NN*3*CC*sizeof(float));
    edge_fwd_k<true><<<EB, 256>>>(Wr, br, h0a, nullptr);
    mm_fwd<<<G1, 256>>>(M0, Wmsg0, h0a, Wself0, b0, nullptr, h0b, s0, NN);
    mm_fwd<<<G3, 256>>>(M1, Wmsg1, nullptr, nullptr, nullptr, nullptr, h1b, nullptr, 3*NN);

    // ---- layer 1 forward (h1 output dead)
    cudaMemsetAsync(M0, 0, NN*CC*sizeof(float));
    cudaMemsetAsync(M1, 0, NN*3*CC*sizeof(float));
    edge_fwd_k<false><<<EB, 256>>>(Wr + 4096, br + 256, h0b, h1b);
    mm_fwd<<<G1, 256>>>(M0, Wmsg0 + 4096, h0b, Wself0 + 4096, b0 + 64, nullptr, h0c, s1, NN);

    // ---- readout backward (fused)
    readout_k<<<G1, 256>>>(h0c, Wro1, bro1, Wro2, gA, NN);

    // ---- layer 1 backward
    mm_bwdT<<<G1, 256>>>(gA, s1, Wmsg0 + 4096, Wself0 + 4096, gM0p, gB, NN);
    cudaMemsetAsync(gh1, 0, NN*3*CC*sizeof(float));
    edge_bwd_k<1><<<EB, 256>>>(Wr + 4096, br + 256, h0b, h1b,
                               gM0p, nullptr, gB, gh1, F);

    // ---- layer 0 backward
    mm_bwdT<<<G1, 256>>>(gB, s0, Wmsg0, nullptr, gM0p, nullptr, NN);
    mm_bwdT<<<G3, 256>>>(gh1, nullptr, Wmsg1, nullptr, gM1p, nullptr, 3*NN);
    edge_bwd_k<0><<<EB, 256>>>(Wr, br, h0a, nullptr,
                               gM0p, gM1p, nullptr, nullptr, F);
}

// round 3
// speedup vs baseline: 1.9865x; 1.1083x over previous
#include <cuda_runtime.h>
#include <math.h>

#define NN   20000
#define EE   320000
#define CC   64
#define NBF  16
#define RCUT 5.0f
#define CSP  (RCUT/(NBF-1))
#define WIDTH (RCUT/NBF)
#define PI_F 3.14159265358979f
#define FULLMASK 0xffffffffu

// ---------------- device scratch ------------------------------------------
static __device__ int   g_cnt;
static __device__ int   g_hist[2*NN];
static __device__ int   g_cur[2*NN];
static __device__ __align__(16) int2   g_Iij[EE];
static __device__ __align__(16) float4 g_Im[EE];
static __device__ __align__(16) int2   g_Jij[EE];
static __device__ __align__(16) float4 g_Jm[EE];

static __device__ __align__(16) float g_h0a[NN*CC];
static __device__ __align__(16) float g_h0b[NN*CC];
static __device__ __align__(16) float g_h0c[NN*CC];
static __device__ __align__(16) float g_s0[NN*CC];
static __device__ __align__(16) float g_s1[NN*CC];
static __device__ __align__(16) float g_h1b[NN*3*CC];
static __device__ __align__(16) float g_M[NN*CC*4];      // M0 | M1
static __device__ __align__(16) float g_gM0[NN*CC];
static __device__ __align__(16) float g_gM1[NN*3*CC];
static __device__ __align__(16) float g_gA[NN*CC];
static __device__ __align__(16) float g_gB[NN*CC];
static __device__ __align__(16) float g_gh1[NN*3*CC];

__device__ __forceinline__ float warpRed(float v){
#pragma unroll
    for(int o=16;o>0;o>>=1) v += __shfl_xor_sync(FULLMASK, v, o);
    return v;
}

__device__ __forceinline__ void red2(float* addr, float a, float b){
    asm volatile("red.global.add.v2.f32 [%0], {%1, %2};"
                 :: "l"(addr), "f"(a), "f"(b) : "memory");
}

// ---------------- geometry pass 1: histograms ------------------------------
__global__ void geomA_k(const float* __restrict__ coord,
                        const int* __restrict__ ei, const int* __restrict__ ej)
{
    int e = blockIdx.x*blockDim.x + threadIdx.x;
    if(e >= EE) return;
    int i = ei[e], j = ej[e];
    float dx = coord[j*3+0] - coord[i*3+0];
    float dy = coord[j*3+1] - coord[i*3+1];
    float dz = coord[j*3+2] - coord[i*3+2];
    float d2 = dx*dx + dy*dy + dz*dz + 1e-12f;
    if(d2 < RCUT*RCUT){
        atomicAdd(&g_hist[i], 1);
        atomicAdd(&g_hist[NN+j], 1);
    }
}

// ---------------- exclusive scans (both halves, one block) -----------------
__global__ __launch_bounds__(1024) void scan_k()
{
    __shared__ int swarp[32];
    int t = threadIdx.x;
    int lane = t & 31, wid = t >> 5;
    for(int pass=0; pass<2; pass++){
        const int* hist = g_hist + pass*NN;
        int* cur = g_cur + pass*NN;
        int base = t*20;
        int local[20];
        int s = 0;
#pragma unroll
        for(int q=0;q<20;q++){
            int idx = base + q;
            int v = (idx < NN) ? hist[idx] : 0;
            local[q] = s; s += v;
        }
        int inc = s;
#pragma unroll
        for(int o=1;o<32;o<<=1){
            int n = __shfl_up_sync(FULLMASK, inc, o);
            if(lane >= o) inc += n;
        }
        if(lane == 31) swarp[wid] = inc;
        __syncthreads();
        if(wid == 0){
            int v = swarp[lane];
#pragma unroll
            for(int o=1;o<32;o<<=1){
                int n = __shfl_up_sync(FULLMASK, v, o);
                if(lane >= o) v += n;
            }
            swarp[lane] = v;
        }
        __syncthreads();
        int offset = inc - s + ((wid > 0) ? swarp[wid-1] : 0);
#pragma unroll
        for(int q=0;q<20;q++){
            int idx = base + q;
            if(idx < NN) cur[idx] = offset + local[q];
        }
        if(pass == 0 && t == 1023) g_cnt = offset + s;
        __syncthreads();
    }
}

// ---------------- geometry pass 2: write both sorted orders ----------------
__global__ void geomB_k(const float* __restrict__ coord,
                        const int* __restrict__ ei, const int* __restrict__ ej)
{
    int e = blockIdx.x*blockDim.x + threadIdx.x;
    if(e >= EE) return;
    int i = ei[e], j = ej[e];
    float dx = coord[j*3+0] - coord[i*3+0];
    float dy = coord[j*3+1] - coord[i*3+1];
    float dz = coord[j*3+2] - coord[i*3+2];
    float d2 = dx*dx + dy*dy + dz*dz + 1e-12f;
    if(d2 >= RCUT*RCUT) return;
    float d = sqrtf(d2);
    float inv = 1.0f/d;
    float4 m = make_float4(d, dx*inv, dy*inv, dz*inv);
    int2 ij = make_int2(i, j);
    int posI = atomicAdd(&g_cur[i], 1);
    g_Iij[posI] = ij;  g_Im[posI] = m;
    int posJ = atomicAdd(&g_cur[NN+j], 1);
    g_Jij[posJ] = ij;  g_Jm[posJ] = m;
}

// ---------------- embedding gather (vectorized) ----------------------------
__global__ void embed_k(const float* __restrict__ emb, const int* __restrict__ z)
{
    int idx = blockIdx.x*blockDim.x + threadIdx.x;
    if(idx >= NN*16) return;
    int n = idx >> 4, q = idx & 15;
    int zn = __ldg(&z[n]);
    float4 v = ((const float4*)emb)[zn*16 + q];
    ((float4*)g_h0a)[idx] = v;
}

// ---------------- forward edge kernel (i-sorted, 8 edges/warp) -------------
template<bool H1Z>
__global__ __launch_bounds__(256) void edge_fwd_k(
    const float* __restrict__ Wr_l, const float* __restrict__ br_l,
    const float* __restrict__ h0,   const float* __restrict__ h1)
{
    constexpr int NP = H1Z ? 2 : 4;
    __shared__ __align__(16) float sWr[NP*NBF*CC];
    __shared__ __align__(16) float sbr[NP*CC];
    int tid = threadIdx.x;
    int cnt = g_cnt;
    if((int)(blockIdx.x*64) >= cnt) return;
    for(int k=tid;k<NP*512;k+=256) ((float2*)sWr)[k] = ((const float2*)Wr_l)[k];
    for(int k=tid;k<NP*64;k+=256) sbr[k] = br_l[k];
    __syncthreads();
    int e0 = (blockIdx.x*8 + (tid>>5))*8;
    if(e0 >= cnt) return;
    int lane = tid & 31;
    int c = 2*lane;
    int eend = min(e0 + 8, cnt);

    float* M0 = g_M;
    float* M1 = g_M + NN*CC;

    float2 a0c = make_float2(0.f,0.f);
    float2 a1c[3] = {{0,0},{0,0},{0,0}};
    int curi = g_Iij[e0].x;

    for(int e=e0;e<eend;e++){
        int2 ij = g_Iij[e];
        if(ij.x != curi){
            red2(&M0[curi*64+c], a0c.x, a0c.y);
#pragma unroll
            for(int x=0;x<3;x++) red2(&M1[(curi*3+x)*64+c], a1c[x].x, a1c[x].y);
            a0c = make_float2(0.f,0.f);
#pragma unroll
            for(int x=0;x<3;x++) a1c[x] = make_float2(0.f,0.f);
            curi = ij.x;
        }
        int j = ij.y;
        float4 m = g_Im[e];
        float d = m.x;
        float rh[3] = {m.y, m.z, m.w};
        float fc = 0.5f*(__cosf(PI_F*d/RCUT) + 1.0f);
        float rb = 0.f;
        if(lane < NBF){
            float zz = (d - lane*CSP)/WIDTH;
            rb = __expf(-zz*zz);
        }
        float2 pre[NP];
#pragma unroll
        for(int p=0;p<NP;p++) pre[p] = *(const float2*)&sbr[p*64+c];
#pragma unroll
        for(int b=0;b<NBF;b++){
            float r = __shfl_sync(FULLMASK, rb, b);
#pragma unroll
            for(int p=0;p<NP;p++){
                float2 w = ((const float2*)sWr)[p*512 + b*32 + lane];
                pre[p].x = fmaf(r, w.x, pre[p].x);
                pre[p].y = fmaf(r, w.y, pre[p].y);
            }
        }
        float2 h0j = *(const float2*)&h0[j*64+c];
        if(H1Z){
            a0c.x = fmaf(fc*pre[0].x, h0j.x, a0c.x);
            a0c.y = fmaf(fc*pre[0].y, h0j.y, a0c.y);
#pragma unroll
            for(int x=0;x<3;x++){
                a1c[x].x = fmaf(fc*pre[1].x*h0j.x, rh[x], a1c[x].x);
                a1c[x].y = fmaf(fc*pre[1].y*h0j.y, rh[x], a1c[x].y);
            }
        } else {
            float2 v[3];
#pragma unroll
            for(int x=0;x<3;x++) v[x] = *(const float2*)&h1[(j*3+x)*64+c];
            float tx = v[0].x*rh[0] + v[1].x*rh[1] + v[2].x*rh[2];
            float ty = v[0].y*rh[0] + v[1].y*rh[1] + v[2].y*rh[2];
            a0c.x += fc*(pre[0].x*h0j.x + pre[2].x*tx);
            a0c.y += fc*(pre[0].y*h0j.y + pre[2].y*ty);
#pragma unroll
            for(int x=0;x<3;x++){
                a1c[x].x += fc*(pre[1].x*h0j.x*rh[x] + pre[3].x*v[x].x);
                a1c[x].y += fc*(pre[1].y*h0j.y*rh[x] + pre[3].y*v[x].y);
            }
        }
    }
    red2(&M0[curi*64+c], a0c.x, a0c.y);
#pragma unroll
    for(int x=0;x<3;x++) red2(&M1[(curi*3+x)*64+c], a1c[x].x, a1c[x].y);
}

// ---------------- backward layer-0 (i-sorted; paths {0,1}; h1==0) ----------
__global__ __launch_bounds__(256) void edge_bwd0_k(
    const float* __restrict__ Wr_l, const float* __restrict__ br_l,
    const float* __restrict__ h0,
    const float* __restrict__ gM0,  const float* __restrict__ gM1,
    float* __restrict__ F)
{
    __shared__ __align__(16) float sW[2*NBF*CC];
    __shared__ __align__(16) float sbr[2*CC];
    int tid = threadIdx.x;
    int cnt = g_cnt;
    if((int)(blockIdx.x*64) >= cnt) return;
    for(int k=tid;k<1024;k+=256) ((float2*)sW)[k] = ((const float2*)Wr_l)[k];  // paths 0,1 contiguous
    for(int k=tid;k<128;k+=256) sbr[k] = br_l[k];
    __syncthreads();
    int e0 = (blockIdx.x*8 + (tid>>5))*8;
    if(e0 >= cnt) return;
    int lane = tid & 31;
    int c = 2*lane;
    int eend = min(e0 + 8, cnt);

    int curi = g_Iij[e0].x;
    float2 gm0 = *(const float2*)&gM0[curi*64+c];
    float2 gm1[3];
#pragma unroll
    for(int x=0;x<3;x++) gm1[x] = *(const float2*)&gM1[(curi*3+x)*64+c];
    float fi = 0.f;

    for(int e=e0;e<eend;e++){
        int2 ij = g_Iij[e];
        if(ij.x != curi){
            if(lane < 3) atomicAdd(&F[curi*3+lane], fi);
            fi = 0.f;
            curi = ij.x;
            gm0 = *(const float2*)&gM0[curi*64+c];
#pragma unroll
            for(int x=0;x<3;x++) gm1[x] = *(const float2*)&gM1[(curi*3+x)*64+c];
        }
        int j = ij.y;
        float4 m = g_Im[e];
        float d = m.x;
        float rh[3] = {m.y, m.z, m.w};
        float fc = 0.5f*(__cosf(PI_F*d/RCUT) + 1.0f);
        float rb = 0.f, wb = 0.f;
        if(lane < NBF){
            float zz = (d - lane*CSP)/WIDTH;
            rb = __expf(-zz*zz);
            wb = rb * (-2.0f*zz/WIDTH);
        }
        float2 preA = *(const float2*)&sbr[c];
        float2 preB = *(const float2*)&sbr[64+c];
        float2 qA = make_float2(0,0), qB = make_float2(0,0);
#pragma unroll
        for(int b=0;b<NBF;b++){
            float r = __shfl_sync(FULLMASK, rb, b);
            float w = __shfl_sync(FULLMASK, wb, b);
            float2 WA = ((const float2*)sW)[b*32 + lane];
            float2 WB = ((const float2*)sW)[512 + b*32 + lane];
            preA.x = fmaf(r, WA.x, preA.x); preA.y = fmaf(r, WA.y, preA.y);
            preB.x = fmaf(r, WB.x, preB.x); preB.y = fmaf(r, WB.y, preB.y);
            qA.x = fmaf(w, WA.x, qA.x); qA.y = fmaf(w, WA.y, qA.y);
            qB.x = fmaf(w, WB.x, qB.x); qB.y = fmaf(w, WB.y, qB.y);
        }
        float2 h0j = *(const float2*)&h0[j*64+c];
        float gmrx = gm1[0].x*rh[0] + gm1[1].x*rh[1] + gm1[2].x*rh[2];
        float gmry = gm1[0].y*rh[0] + gm1[1].y*rh[1] + gm1[2].y*rh[2];

        float gf0x = gm0.x*h0j.x, gf0y = gm0.y*h0j.y;
        float gf1x = gmrx*h0j.x,  gf1y = gmry*h0j.y;
        float sfc = gf0x*preA.x + gf0y*preA.y + gf1x*preB.x + gf1y*preB.y;
        float sd  = gf0x*qA.x   + gf0y*qA.y   + gf1x*qB.x   + gf1y*qB.y;
        float f1x = fc*preB.x*h0j.x, f1y = fc*preB.y*h0j.y;
        float gr0 = gm1[0].x*f1x + gm1[0].y*f1y;
        float gr1 = gm1[1].x*f1x + gm1[1].y*f1y;
        float gr2 = gm1[2].x*f1x + gm1[2].y*f1y;

        sfc = warpRed(sfc);
        sd  = warpRed(sd);
        gr0 = warpRed(gr0);
        gr1 = warpRed(gr1);
        gr2 = warpRed(gr2);

        float dfc = -0.5f*(PI_F/RCUT)*__sinf(PI_F*d/RCUT);
        float gd  = fc*sd + sfc*dfc;
        float gdr = gr0*rh[0] + gr1*rh[1] + gr2*rh[2];
        float invd = 1.0f/d;
        if(lane < 3){
            float gx = (lane==0) ? gr0 : ((lane==1) ? gr1 : gr2);
            float rx = rh[lane];
            float grij = (gx - gdr*rx)*invd + gd*rx;
            fi += grij;
            atomicAdd(&F[j*3+lane], -grij);
        }
    }
    if(lane < 3) atomicAdd(&F[curi*3+lane], fi);
}

// ---------------- backward layer-1 (j-sorted; paths {0,2}) -----------------
__global__ __launch_bounds__(256) void edge_bwd1_k(
    const float* __restrict__ Wr_l, const float* __restrict__ br_l,
    const float* __restrict__ h0,   const float* __restrict__ h1,
    const float* __restrict__ gM0,
    float* __restrict__ gh0, float* __restrict__ gh1, float* __restrict__ F)
{
    __shared__ __align__(16) float sW[2*NBF*CC];
    __shared__ __align__(16) float sbr[2*CC];
    int tid = threadIdx.x;
    int cnt = g_cnt;
    if((int)(blockIdx.x*64) >= cnt) return;
    for(int k=tid;k<512;k+=256) ((float2*)sW)[k] = ((const float2*)Wr_l)[k];            // path 0
    for(int k=tid;k<512;k+=256) ((float2*)sW)[512+k] = ((const float2*)(Wr_l+2048))[k]; // path 2
    for(int k=tid;k<64;k+=256){ sbr[k] = br_l[k]; sbr[64+k] = br_l[128+k]; }
    __syncthreads();
    int e0 = (blockIdx.x*8 + (tid>>5))*8;
    if(e0 >= cnt) return;
    int lane = tid & 31;
    int c = 2*lane;
    int eend = min(e0 + 8, cnt);

    int curj = g_Jij[e0].y;
    float2 h0j = *(const float2*)&h0[curj*64+c];
    float2 v[3];
#pragma unroll
    for(int x=0;x<3;x++) v[x] = *(const float2*)&h1[(curj*3+x)*64+c];
    float2 acc0 = make_float2(0,0);
    float2 acc1[3] = {{0,0},{0,0},{0,0}};
    float fj = 0.f;

    for(int e=e0;e<eend;e++){
        int2 ij = g_Jij[e];
        if(ij.y != curj){
            red2(&gh0[curj*64+c], acc0.x, acc0.y);
#pragma unroll
            for(int x=0;x<3;x++) red2(&gh1[(curj*3+x)*64+c], acc1[x].x, acc1[x].y);
            if(lane < 3) atomicAdd(&F[curj*3+lane], fj);
            acc0 = make_float2(0,0);
#pragma unroll
            for(int x=0;x<3;x++) acc1[x] = make_float2(0,0);
            fj = 0.f;
            curj = ij.y;
            h0j = *(const float2*)&h0[curj*64+c];
#pragma unroll
            for(int x=0;x<3;x++) v[x] = *(const float2*)&h1[(curj*3+x)*64+c];
        }
        int i = ij.x;
        float4 m = g_Jm[e];
        float d = m.x;
        float rh[3] = {m.y, m.z, m.w};
        float fc = 0.5f*(__cosf(PI_F*d/RCUT) + 1.0f);
        float rb = 0.f, wb = 0.f;
        if(lane < NBF){
            float zz = (d - lane*CSP)/WIDTH;
            rb = __expf(-zz*zz);
            wb = rb * (-2.0f*zz/WIDTH);
        }
        float2 preA = *(const float2*)&sbr[c];
        float2 preB = *(const float2*)&sbr[64+c];
        float2 qA = make_float2(0,0), qB = make_float2(0,0);
#pragma unroll
        for(int b=0;b<NBF;b++){
            float r = __shfl_sync(FULLMASK, rb, b);
            float w = __shfl_sync(FULLMASK, wb, b);
            float2 WA = ((const float2*)sW)[b*32 + lane];
            float2 WB = ((const float2*)sW)[512 + b*32 + lane];
            preA.x = fmaf(r, WA.x, preA.x); preA.y = fmaf(r, WA.y, preA.y);
            preB.x = fmaf(r, WB.x, preB.x); preB.y = fmaf(r, WB.y, preB.y);
            qA.x = fmaf(w, WA.x, qA.x); qA.y = fmaf(w, WA.y, qA.y);
            qB.x = fmaf(w, WB.x, qB.x); qB.y = fmaf(w, WB.y, qB.y);
        }
        float2 gm0 = *(const float2*)&gM0[i*64+c];
        float tx = v[0].x*rh[0] + v[1].x*rh[1] + v[2].x*rh[2];
        float ty = v[0].y*rh[0] + v[1].y*rh[1] + v[2].y*rh[2];

        float gf0x = gm0.x*h0j.x, gf0y = gm0.y*h0j.y;
        float gf2x = gm0.x*tx,    gf2y = gm0.y*ty;
        float sfc = gf0x*preA.x + gf0y*preA.y + gf2x*preB.x + gf2y*preB.y;
        float sd  = gf0x*qA.x   + gf0y*qA.y   + gf2x*qB.x   + gf2y*qB.y;
        float f2x = fc*preB.x*gm0.x, f2y = fc*preB.y*gm0.y;
        float gr0 = f2x*v[0].x + f2y*v[0].y;
        float gr1 = f2x*v[1].x + f2y*v[1].y;
        float gr2 = f2x*v[2].x + f2y*v[2].y;

        acc0.x += gm0.x*fc*preA.x;
        acc0.y += gm0.y*fc*preA.y;
#pragma unroll
        for(int x=0;x<3;x++){
            acc1[x].x += f2x*rh[x];
            acc1[x].y += f2y*rh[x];
        }

        sfc = warpRed(sfc);
        sd  = warpRed(sd);
        gr0 = warpRed(gr0);
        gr1 = warpRed(gr1);
        gr2 = warpRed(gr2);

        float dfc = -0.5f*(PI_F/RCUT)*__sinf(PI_F*d/RCUT);
        float gd  = fc*sd + sfc*dfc;
        float gdr = gr0*rh[0] + gr1*rh[1] + gr2*rh[2];
        float invd = 1.0f/d;
        if(lane < 3){
            float gx = (lane==0) ? gr0 : ((lane==1) ? gr1 : gr2);
            float rx = rh[lane];
            float grij = (gx - gdr*rx)*invd + gd*rx;
            atomicAdd(&F[i*3+lane], grij);
            fj -= grij;
        }
    }
    red2(&gh0[curj*64+c], acc0.x, acc0.y);
#pragma unroll
    for(int x=0;x<3;x++) red2(&gh1[(curj*3+x)*64+c], acc1[x].x, acc1[x].y);
    if(lane < 3) atomicAdd(&F[curj*3+lane], fj);
}

// ---------------- node GEMM: out = epilogue(A@W1 [+ B@W2] [+ bias]) --------
__global__ __launch_bounds__(256) void mm_fwd(
    const float* __restrict__ A, const float* __restrict__ W1,
    const float* __restrict__ B, const float* __restrict__ W2,
    const float* __restrict__ bias, const float* __restrict__ ro2,
    float* __restrict__ out, float* __restrict__ sOut, int rows)
{
    __shared__ float sW[64*64];
    __shared__ float sX[64*65];
    int tid = threadIdx.x;
    int row0 = blockIdx.x*64;
    int tc = tid & 15, tr = tid >> 4;
    float acc[4][4];
    if(bias){
        float4 b = *(const float4*)&bias[4*tc];
#pragma unroll
        for(int i=0;i<4;i++){ acc[i][0]=b.x; acc[i][1]=b.y; acc[i][2]=b.z; acc[i][3]=b.w; }
    } else {
#pragma unroll
        for(int i=0;i<4;i++){ acc[i][0]=acc[i][1]=acc[i][2]=acc[i][3]=0.f; }
    }
    int nph = B ? 2 : 1;
    for(int ph=0; ph<nph; ph++){
        const float* Xp = ph ? B : A;
        const float* Wp = ph ? W2 : W1;
        if(ph) __syncthreads();
        for(int k=tid;k<4096;k+=256) sW[k] = Wp[k];
        for(int k=tid;k<4096;k+=256){
            int r = k>>6, c = k&63;
            int gr = row0 + r;
            sX[r*65+c] = (gr < rows) ? Xp[gr*64+c] : 0.f;
        }
        __syncthreads();
        const float* xr = &sX[(tr*4)*65];
#pragma unroll 8
        for(int k=0;k<64;k++){
            float a0 = xr[k], a1 = xr[65+k], a2 = xr[130+k], a3 = xr[195+k];
            float4 w = *(const float4*)&sW[k*64 + tc*4];
            acc[0][0]=fmaf(a0,w.x,acc[0][0]); acc[0][1]=fmaf(a0,w.y,acc[0][1]);
            acc[0][2]=fmaf(a0,w.z,acc[0][2]); acc[0][3]=fmaf(a0,w.w,acc[0][3]);
            acc[1][0]=fmaf(a1,w.x,acc[1][0]); acc[1][1]=fmaf(a1,w.y,acc[1][1]);
            acc[1][2]=fmaf(a1,w.z,acc[1][2]); acc[1][3]=fmaf(a1,w.w,acc[1][3]);
            acc[2][0]=fmaf(a2,w.x,acc[2][0]); acc[2][1]=fmaf(a2,w.y,acc[2][1]);
            acc[2][2]=fmaf(a2,w.z,acc[2][2]); acc[2][3]=fmaf(a2,w.w,acc[2][3]);
            acc[3][0]=fmaf(a3,w.x,acc[3][0]); acc[3][1]=fmaf(a3,w.y,acc[3][1]);
            acc[3][2]=fmaf(a3,w.z,acc[3][2]); acc[3][3]=fmaf(a3,w.w,acc[3][3]);
        }
    }
    float4 ro2v = make_float4(0,0,0,0);
    if(ro2) ro2v = *(const float4*)&ro2[4*tc];
#pragma unroll
    for(int i=0;i<4;i++){
        int r = row0 + tr*4 + i;
        if(r >= rows) continue;
        float4 o;
        float* oo = &o.x;
#pragma unroll
        for(int jj=0;jj<4;jj++){
            float u = acc[i][jj];
            float val;
            if(ro2){
                float sig = 1.f/(1.f + expf(-u));
                float rr = (&ro2v.x)[jj];
                val = rr*sig*fmaf(u, 1.f-sig, 1.f);
            } else if(sOut){
                float sig = 1.f/(1.f + expf(-u));
                val = u*sig;
            } else {
                val = u;
            }
            oo[jj] = val;
        }
        if(sOut){
            float4 so = make_float4(acc[i][0],acc[i][1],acc[i][2],acc[i][3]);
            *(float4*)&sOut[r*64 + tc*4] = so;
        }
        *(float4*)&out[r*64 + tc*4] = o;
    }
}

// ---------------- node GEMM transposed with fused dsilu --------------------
__global__ __launch_bounds__(256) void mm_bwdT(
    const float* __restrict__ G, const float* __restrict__ S,
    const float* __restrict__ W1, const float* __restrict__ W2,
    float* __restrict__ out1, float* __restrict__ out2, int rows)
{
    __shared__ float sWt[64*68];
    __shared__ float sG[64*65];
    int tid = threadIdx.x;
    int row0 = blockIdx.x*64;
    int tc = tid & 15, tr = tid >> 4;
    for(int k=tid;k<4096;k+=256){
        int r = k>>6, c = k&63;
        int gr = row0 + r;
        float v = 0.f;
        if(gr < rows){
            float g = G[gr*64+c];
            if(S){
                float x = S[gr*64+c];
                float sig = 1.f/(1.f + expf(-x));
                v = g*sig*fmaf(x, 1.f-sig, 1.f);
            } else v = g;
        }
        sG[r*65+c] = v;
    }
    int nph = out2 ? 2 : 1;
    for(int ph=0; ph<nph; ph++){
        const float* Wp = ph ? W2 : W1;
        float* op = ph ? out2 : out1;
        if(ph) __syncthreads();
        for(int k=tid;k<4096;k+=256){
            int cout = k>>6, dd = k&63;
            sWt[dd*68+cout] = Wp[k];
        }
        __syncthreads();
        float acc[4][4];
#pragma unroll
        for(int i=0;i<4;i++){ acc[i][0]=acc[i][1]=acc[i][2]=acc[i][3]=0.f; }
        const float* xr = &sG[(tr*4)*65];
#pragma unroll 8
        for(int k=0;k<64;k++){
            float a0 = xr[k], a1 = xr[65+k], a2 = xr[130+k], a3 = xr[195+k];
            float4 w = *(const float4*)&sWt[k*68 + tc*4];
            acc[0][0]=fmaf(a0,w.x,acc[0][0]); acc[0][1]=fmaf(a0,w.y,acc[0][1]);
            acc[0][2]=fmaf(a0,w.z,acc[0][2]); acc[0][3]=fmaf(a0,w.w,acc[0][3]);
            acc[1][0]=fmaf(a1,w.x,acc[1][0]); acc[1][1]=fmaf(a1,w.y,acc[1][1]);
            acc[1][2]=fmaf(a1,w.z,acc[1][2]); acc[1][3]=fmaf(a1,w.w,acc[1][3]);
            acc[2][0]=fmaf(a2,w.x,acc[2][0]); acc[2][1]=fmaf(a2,w.y,acc[2][1]);
            acc[2][2]=fmaf(a2,w.z,acc[2][2]); acc[2][3]=fmaf(a2,w.w,acc[2][3]);
            acc[3][0]=fmaf(a3,w.x,acc[3][0]); acc[3][1]=fmaf(a3,w.y,acc[3][1]);
            acc[3][2]=fmaf(a3,w.z,acc[3][2]); acc[3][3]=fmaf(a3,w.w,acc[3][3]);
        }
#pragma unroll
        for(int i=0;i<4;i++){
            int r = row0 + tr*4 + i;
            if(r >= rows) continue;
            float4 o = make_float4(acc[i][0],acc[i][1],acc[i][2],acc[i][3]);
            *(float4*)&op[r*64 + tc*4] = o;
        }
    }
}

// ---------------- fused readout backward -----------------------------------
__global__ __launch_bounds__(256) void readout_k(
    const float* __restrict__ A, const float* __restrict__ Wro1,
    const float* __restrict__ bro1, const float* __restrict__ Wro2,
    float* __restrict__ gA, int rows)
{
    __shared__ float sW[64*68];
    __shared__ float sX[64*65];
    int tid = threadIdx.x;
    int row0 = blockIdx.x*64;
    int tc = tid & 15, tr = tid >> 4;
    for(int k=tid;k<4096;k+=256) sW[k] = Wro1[k];
    for(int k=tid;k<4096;k+=256){
        int r = k>>6, c = k&63;
        int gr = row0 + r;
        sX[r*65+c] = (gr < rows) ? A[gr*64+c] : 0.f;
    }
    __syncthreads();
    float acc[4][4];
    {
        float4 b = *(const float4*)&bro1[4*tc];
#pragma unroll
        for(int i=0;i<4;i++){ acc[i][0]=b.x; acc[i][1]=b.y; acc[i][2]=b.z; acc[i][3]=b.w; }
    }
    {
        const float* xr = &sX[(tr*4)*65];
#pragma unroll 8
        for(int k=0;k<64;k++){
            float a0 = xr[k], a1 = xr[65+k], a2 = xr[130+k], a3 = xr[195+k];
            float4 w = *(const float4*)&sW[k*64 + tc*4];
            acc[0][0]=fmaf(a0,w.x,acc[0][0]); acc[0][1]=fmaf(a0,w.y,acc[0][1]);
            acc[0][2]=fmaf(a0,w.z,acc[0][2]); acc[0][3]=fmaf(a0,w.w,acc[0][3]);
            acc[1][0]=fmaf(a1,w.x,acc[1][0]); acc[1][1]=fmaf(a1,w.y,acc[1][1]);
            acc[1][2]=fmaf(a1,w.z,acc[1][2]); acc[1][3]=fmaf(a1,w.w,acc[1][3]);
            acc[2][0]=fmaf(a2,w.x,acc[2][0]); acc[2][1]=fmaf(a2,w.y,acc[2][1]);
            acc[2][2]=fmaf(a2,w.z,acc[2][2]); acc[2][3]=fmaf(a2,w.w,acc[2][3]);
            acc[3][0]=fmaf(a3,w.x,acc[3][0]); acc[3][1]=fmaf(a3,w.y,acc[3][1]);
            acc[3][2]=fmaf(a3,w.z,acc[3][2]); acc[3][3]=fmaf(a3,w.w,acc[3][3]);
        }
    }
    __syncthreads();
    {
        float4 ro2v = *(const float4*)&Wro2[4*tc];
#pragma unroll
        for(int i=0;i<4;i++){
#pragma unroll
            for(int jj=0;jj<4;jj++){
                float u = acc[i][jj];
                float sig = 1.f/(1.f + expf(-u));
                float w = (&ro2v.x)[jj]*sig*fmaf(u, 1.f-sig, 1.f);
                sX[(tr*4+i)*65 + tc*4 + jj] = w;
            }
        }
    }
    for(int k=tid;k<4096;k+=256){
        int cout = k>>6, dd = k&63;
        sW[dd*68+cout] = Wro1[k];
    }
    __syncthreads();
    float acc2[4][4];
#pragma unroll
    for(int i=0;i<4;i++){ acc2[i][0]=acc2[i][1]=acc2[i][2]=acc2[i][3]=0.f; }
    {
        const float* xr = &sX[(tr*4)*65];
#pragma unroll 8
        for(int k=0;k<64;k++){
            float a0 = xr[k], a1 = xr[65+k], a2 = xr[130+k], a3 = xr[195+k];
            float4 w = *(const float4*)&sW[k*68 + tc*4];
            acc2[0][0]=fmaf(a0,w.x,acc2[0][0]); acc2[0][1]=fmaf(a0,w.y,acc2[0][1]);
            acc2[0][2]=fmaf(a0,w.z,acc2[0][2]); acc2[0][3]=fmaf(a0,w.w,acc2[0][3]);
            acc2[1][0]=fmaf(a1,w.x,acc2[1][0]); acc2[1][1]=fmaf(a1,w.y,acc2[1][1]);
            acc2[1][2]=fmaf(a1,w.z,acc2[1][2]); acc2[1][3]=fmaf(a1,w.w,acc2[1][3]);
            acc2[2][0]=fmaf(a2,w.x,acc2[2][0]); acc2[2][1]=fmaf(a2,w.y,acc2[2][1]);
            acc2[2][2]=fmaf(a2,w.z,acc2[2][2]); acc2[2][3]=fmaf(a2,w.w,acc2[2][3]);
            acc2[3][0]=fmaf(a3,w.x,acc2[3][0]); acc2[3][1]=fmaf(a3,w.y,acc2[3][1]);
            acc2[3][2]=fmaf(a3,w.z,acc2[3][2]); acc2[3][3]=fmaf(a3,w.w,acc2[3][3]);
        }
    }
#pragma unroll
    for(int i=0;i<4;i++){
        int r = row0 + tr*4 + i;
        if(r >= rows) continue;
        float4 o = make_float4(acc2[i][0],acc2[i][1],acc2[i][2],acc2[i][3]);
        *(float4*)&gA[r*64 + tc*4] = o;
    }
}

// ---------------- host orchestration ---------------------------------------
extern "C" void kernel_launch(void* const* d_in, const int* in_sizes, int n_in,
                              void* d_out, int out_size)
{
    const float* coord  = (const float*)d_in[0];
    const float* emb    = (const float*)d_in[1];
    const float* Wr     = (const float*)d_in[2];
    const float* br     = (const float*)d_in[3];
    const float* Wself0 = (const float*)d_in[4];
    const float* Wmsg0  = (const float*)d_in[5];
    const float* b0     = (const float*)d_in[6];
    const float* Wmsg1  = (const float*)d_in[7];
    const float* Wro1   = (const float*)d_in[9];
    const float* bro1   = (const float*)d_in[10];
    const float* Wro2   = (const float*)d_in[11];
    const int*   z      = (const int*)d_in[13];
    const int*   ei     = (const int*)d_in[14];
    const int*   ej     = (const int*)d_in[15];
    float* F = (float*)d_out;
    (void)in_sizes; (void)n_in; (void)out_size;

    void *phist;
    float *h0a,*h0b,*h0c,*s0,*s1,*h1b,*Mbuf,*gM0p,*gM1p,*gA,*gB,*gh1;
    cudaGetSymbolAddress(&phist, g_hist);
    cudaGetSymbolAddress((void**)&h0a, g_h0a);
    cudaGetSymbolAddress((void**)&h0b, g_h0b);
    cudaGetSymbolAddress((void**)&h0c, g_h0c);
    cudaGetSymbolAddress((void**)&s0,  g_s0);
    cudaGetSymbolAddress((void**)&s1,  g_s1);
    cudaGetSymbolAddress((void**)&h1b, g_h1b);
    cudaGetSymbolAddress((void**)&Mbuf,g_M);
    cudaGetSymbolAddress((void**)&gM0p,g_gM0);
    cudaGetSymbolAddress((void**)&gM1p,g_gM1);
    cudaGetSymbolAddress((void**)&gA,  g_gA);
    cudaGetSymbolAddress((void**)&gB,  g_gB);
    cudaGetSymbolAddress((void**)&gh1, g_gh1);
    float* M0 = Mbuf;
    float* M1 = Mbuf + NN*CC;

    const int EB  = (EE + 63)/64;
    const int G1  = (NN + 63)/64;
    const int G3  = (3*NN + 63)/64;

    cudaMemsetAsync(phist, 0, 2*NN*sizeof(int));
    cudaMemsetAsync(F, 0, NN*3*sizeof(float));
    geomA_k<<<(EE+255)/256, 256>>>(coord, ei, ej);
    scan_k<<<1, 1024>>>();
    geomB_k<<<(EE+255)/256, 256>>>(coord, ei, ej);
    embed_k<<<(NN*16+255)/256, 256>>>(emb, z);

    // ---- layer 0 forward
    cudaMemsetAsync(Mbuf, 0, NN*CC*4*sizeof(float));
    edge_fwd_k<true><<<EB, 256>>>(Wr, br, h0a, nullptr);
    mm_fwd<<<G1, 256>>>(M0, Wmsg0, h0a, Wself0, b0, nullptr, h0b, s0, NN);
    mm_fwd<<<G3, 256>>>(M1, Wmsg1, nullptr, nullptr, nullptr, nullptr, h1b, nullptr, 3*NN);

    // ---- layer 1 forward (h1 output dead)
    cudaMemsetAsync(Mbuf, 0, NN*CC*4*sizeof(float));
    edge_fwd_k<false><<<EB, 256>>>(Wr + 4096, br + 256, h0b, h1b);
    mm_fwd<<<G1, 256>>>(M0, Wmsg0 + 4096, h0b, Wself0 + 4096, b0 + 64, nullptr, h0c, s1, NN);

    // ---- readout backward (fused)
    readout_k<<<G1, 256>>>(h0c, Wro1, bro1, Wro2, gA, NN);

    // ---- layer 1 backward (j-sorted scatter)
    mm_bwdT<<<G1, 256>>>(gA, s1, Wmsg0 + 4096, Wself0 + 4096, gM0p, gB, NN);
    cudaMemsetAsync(gh1, 0, NN*3*CC*sizeof(float));
    edge_bwd1_k<<<EB, 256>>>(Wr + 4096, br + 256, h0b, h1b, gM0p, gB, gh1, F);

    // ---- layer 0 backward (i-sorted)
    mm_bwdT<<<G1, 256>>>(gB, s0, Wmsg0, nullptr, gM0p, nullptr, NN);
    mm_bwdT<<<G3, 256>>>(gh1, nullptr, Wmsg1, nullptr, gM1p, nullptr, 3*NN);
    edge_bwd0_k<<<EB, 256>>>(Wr, br, h0a, gM0p, gM1p, F);
}

// round 4
// speedup vs baseline: 2.0388x; 1.0264x over previous
#include <cuda_runtime.h>
#include <math.h>

#define NN   20000
#define EE   320000
#define CC   64
#define NBF  16
#define RCUT 5.0f
#define CSP  (RCUT/(NBF-1))
#define WIDTH (RCUT/NBF)
#define PI_F 3.14159265358979f
#define FULLMASK 0xffffffffu

// ---------------- device scratch ------------------------------------------
static __device__ int   g_cnt;
static __device__ int   g_hist[2*NN];
static __device__ int   g_cur[2*NN];
static __device__ __align__(16) int2   g_Iij[EE];
static __device__ __align__(16) float4 g_Im[EE];
static __device__ __align__(16) int2   g_Jij[EE];
static __device__ __align__(16) float4 g_Jm[EE];

static __device__ __align__(16) float g_h0a[NN*CC];
static __device__ __align__(16) float g_h0b[NN*CC];
static __device__ __align__(16) float g_h0c[NN*CC];
static __device__ __align__(16) float g_s0[NN*CC];
static __device__ __align__(16) float g_s1[NN*CC];
static __device__ __align__(16) float g_h1b[NN*3*CC];
static __device__ __align__(16) float g_M[NN*CC*4];      // M0 | M1
static __device__ __align__(16) float g_gM0[NN*CC];
static __device__ __align__(16) float g_gM1[NN*3*CC];
static __device__ __align__(16) float g_gA[NN*CC];
static __device__ __align__(16) float g_gB[NN*CC];
static __device__ __align__(16) float g_gh1[NN*3*CC];

__device__ __forceinline__ float warpRed(float v){
#pragma unroll
    for(int o=16;o>0;o>>=1) v += __shfl_xor_sync(FULLMASK, v, o);
    return v;
}

__device__ __forceinline__ void red2(float* addr, float a, float b){
    asm volatile("red.global.add.v2.f32 [%0], {%1, %2};"
                 :: "l"(addr), "f"(a), "f"(b) : "memory");
}

// ---------------- geometry pass 1: histograms ------------------------------
__global__ void geomA_k(const float* __restrict__ coord,
                        const int* __restrict__ ei, const int* __restrict__ ej)
{
    int e = blockIdx.x*blockDim.x + threadIdx.x;
    if(e >= EE) return;
    int i = ei[e], j = ej[e];
    float dx = coord[j*3+0] - coord[i*3+0];
    float dy = coord[j*3+1] - coord[i*3+1];
    float dz = coord[j*3+2] - coord[i*3+2];
    float d2 = dx*dx + dy*dy + dz*dz + 1e-12f;
    if(d2 < RCUT*RCUT){
        atomicAdd(&g_hist[i], 1);
        atomicAdd(&g_hist[NN+j], 1);
    }
}

// ---------------- exclusive scans (both halves, one block) -----------------
__global__ __launch_bounds__(1024) void scan_k()
{
    __shared__ int swarp[32];
    int t = threadIdx.x;
    int lane = t & 31, wid = t >> 5;
    for(int pass=0; pass<2; pass++){
        const int* hist = g_hist + pass*NN;
        int* cur = g_cur + pass*NN;
        int base = t*20;
        int local[20];
        int s = 0;
#pragma unroll
        for(int q=0;q<20;q++){
            int idx = base + q;
            int v = (idx < NN) ? hist[idx] : 0;
            local[q] = s; s += v;
        }
        int inc = s;
#pragma unroll
        for(int o=1;o<32;o<<=1){
            int n = __shfl_up_sync(FULLMASK, inc, o);
            if(lane >= o) inc += n;
        }
        if(lane == 31) swarp[wid] = inc;
        __syncthreads();
        if(wid == 0){
            int v = swarp[lane];
#pragma unroll
            for(int o=1;o<32;o<<=1){
                int n = __shfl_up_sync(FULLMASK, v, o);
                if(lane >= o) v += n;
            }
            swarp[lane] = v;
        }
        __syncthreads();
        int offset = inc - s + ((wid > 0) ? swarp[wid-1] : 0);
#pragma unroll
        for(int q=0;q<20;q++){
            int idx = base + q;
            if(idx < NN) cur[idx] = offset + local[q];
        }
        if(pass == 0 && t == 1023) g_cnt = offset + s;
        __syncthreads();
    }
}

// ---------------- geometry pass 2: write both sorted orders ----------------
__global__ void geomB_k(const float* __restrict__ coord,
                        const int* __restrict__ ei, const int* __restrict__ ej)
{
    int e = blockIdx.x*blockDim.x + threadIdx.x;
    if(e >= EE) return;
    int i = ei[e], j = ej[e];
    float dx = coord[j*3+0] - coord[i*3+0];
    float dy = coord[j*3+1] - coord[i*3+1];
    float dz = coord[j*3+2] - coord[i*3+2];
    float d2 = dx*dx + dy*dy + dz*dz + 1e-12f;
    if(d2 >= RCUT*RCUT) return;
    float d = sqrtf(d2);
    float inv = 1.0f/d;
    float4 m = make_float4(d, dx*inv, dy*inv, dz*inv);
    int2 ij = make_int2(i, j);
    int posI = atomicAdd(&g_cur[i], 1);
    g_Iij[posI] = ij;  g_Im[posI] = m;
    int posJ = atomicAdd(&g_cur[NN+j], 1);
    g_Jij[posJ] = ij;  g_Jm[posJ] = m;
}

// ---------------- embedding gather (vectorized, grid-stride) ---------------
__global__ void embed_k(const float* __restrict__ emb, const int* __restrict__ z)
{
    for(int idx = blockIdx.x*blockDim.x + threadIdx.x; idx < NN*16;
        idx += gridDim.x*blockDim.x){
        int n = idx >> 4, q = idx & 15;
        int zn = __ldg(&z[n]);
        ((float4*)g_h0a)[idx] = ((const float4*)emb)[zn*16 + q];
    }
}

// ---------------- forward layer-0 edge kernel (i-sorted; paths {0,1}) ------
__global__ __launch_bounds__(128) void edge_fwd0_k(
    const float* __restrict__ Wr_l, const float* __restrict__ br_l,
    const float* __restrict__ h0)
{
    int tid = threadIdx.x;
    int cnt = g_cnt;
    int e0 = (blockIdx.x*4 + (tid>>5))*8;
    if(e0 >= cnt) return;
    int lane = tid & 31;
    int c = 2*lane;
    int eend = min(e0 + 8, cnt);

    float2 WA[NBF], WB[NBF];
    const float2* wa = (const float2*)Wr_l;          // path 0
    const float2* wb = (const float2*)Wr_l + 512;    // path 1
#pragma unroll
    for(int b=0;b<NBF;b++){ WA[b] = wa[b*32+lane]; WB[b] = wb[b*32+lane]; }
    float2 bA = ((const float2*)br_l)[lane];
    float2 bB = ((const float2*)br_l)[32+lane];

    float* M0 = g_M;
    float* M1 = g_M + NN*CC;

    float2 a0c = make_float2(0.f,0.f);
    float2 a1c[3] = {{0,0},{0,0},{0,0}};
    int curi = g_Iij[e0].x;

    for(int e=e0;e<eend;e++){
        int2 ij = g_Iij[e];
        if(ij.x != curi){
            red2(&M0[curi*64+c], a0c.x, a0c.y);
#pragma unroll
            for(int x=0;x<3;x++) red2(&M1[(curi*3+x)*64+c], a1c[x].x, a1c[x].y);
            a0c = make_float2(0.f,0.f);
#pragma unroll
            for(int x=0;x<3;x++) a1c[x] = make_float2(0.f,0.f);
            curi = ij.x;
        }
        int j = ij.y;
        float4 m = g_Im[e];
        float d = m.x;
        float rh[3] = {m.y, m.z, m.w};
        float fc = 0.5f*(__cosf(PI_F*d/RCUT) + 1.0f);
        float rb = 0.f;
        if(lane < NBF){
            float zz = (d - lane*CSP)/WIDTH;
            rb = __expf(-zz*zz);
        }
        float2 p0 = bA, p1 = bB;
#pragma unroll
        for(int b=0;b<NBF;b++){
            float r = __shfl_sync(FULLMASK, rb, b);
            p0.x = fmaf(r, WA[b].x, p0.x); p0.y = fmaf(r, WA[b].y, p0.y);
            p1.x = fmaf(r, WB[b].x, p1.x); p1.y = fmaf(r, WB[b].y, p1.y);
        }
        float2 h0j = *(const float2*)&h0[j*64+c];
        a0c.x = fmaf(fc*p0.x, h0j.x, a0c.x);
        a0c.y = fmaf(fc*p0.y, h0j.y, a0c.y);
        float g1x = fc*p1.x*h0j.x, g1y = fc*p1.y*h0j.y;
#pragma unroll
        for(int x=0;x<3;x++){
            a1c[x].x = fmaf(g1x, rh[x], a1c[x].x);
            a1c[x].y = fmaf(g1y, rh[x], a1c[x].y);
        }
    }
    red2(&M0[curi*64+c], a0c.x, a0c.y);
#pragma unroll
    for(int x=0;x<3;x++) red2(&M1[(curi*3+x)*64+c], a1c[x].x, a1c[x].y);
}

// ---------------- forward layer-1 edge kernel (i-sorted; paths {0,2}) ------
// M1 output is dead at layer 1 — only M0 accumulated.
__global__ __launch_bounds__(128) void edge_fwd1_k(
    const float* __restrict__ Wr_l, const float* __restrict__ br_l,
    const float* __restrict__ h0,   const float* __restrict__ h1)
{
    int tid = threadIdx.x;
    int cnt = g_cnt;
    int e0 = (blockIdx.x*4 + (tid>>5))*8;
    if(e0 >= cnt) return;
    int lane = tid & 31;
    int c = 2*lane;
    int eend = min(e0 + 8, cnt);

    float2 WA[NBF], WB[NBF];
    const float2* wa = (const float2*)Wr_l;           // path 0
    const float2* wb = (const float2*)Wr_l + 1024;    // path 2
#pragma unroll
    for(int b=0;b<NBF;b++){ WA[b] = wa[b*32+lane]; WB[b] = wb[b*32+lane]; }
    float2 bA = ((const float2*)br_l)[lane];
    float2 bB = ((const float2*)br_l)[64+lane];

    float* M0 = g_M;
    float2 a0c = make_float2(0.f,0.f);
    int curi = g_Iij[e0].x;

    for(int e=e0;e<eend;e++){
        int2 ij = g_Iij[e];
        if(ij.x != curi){
            red2(&M0[curi*64+c], a0c.x, a0c.y);
            a0c = make_float2(0.f,0.f);
            curi = ij.x;
        }
        int j = ij.y;
        float4 m = g_Im[e];
        float d = m.x;
        float rh[3] = {m.y, m.z, m.w};
        float fc = 0.5f*(__cosf(PI_F*d/RCUT) + 1.0f);
        float rb = 0.f;
        if(lane < NBF){
            float zz = (d - lane*CSP)/WIDTH;
            rb = __expf(-zz*zz);
        }
        float2 p0 = bA, p2 = bB;
#pragma unroll
        for(int b=0;b<NBF;b++){
            float r = __shfl_sync(FULLMASK, rb, b);
            p0.x = fmaf(r, WA[b].x, p0.x); p0.y = fmaf(r, WA[b].y, p0.y);
            p2.x = fmaf(r, WB[b].x, p2.x); p2.y = fmaf(r, WB[b].y, p2.y);
        }
        float2 h0j = *(const float2*)&h0[j*64+c];
        float2 v[3];
#pragma unroll
        for(int x=0;x<3;x++) v[x] = *(const float2*)&h1[(j*3+x)*64+c];
        float tx = v[0].x*rh[0] + v[1].x*rh[1] + v[2].x*rh[2];
        float ty = v[0].y*rh[0] + v[1].y*rh[1] + v[2].y*rh[2];
        a0c.x += fc*(p0.x*h0j.x + p2.x*tx);
        a0c.y += fc*(p0.y*h0j.y + p2.y*ty);
    }
    red2(&M0[curi*64+c], a0c.x, a0c.y);
}

// ---------------- backward layer-0 (i-sorted; paths {0,1}; h1==0) ----------
__global__ __launch_bounds__(128) void edge_bwd0_k(
    const float* __restrict__ Wr_l, const float* __restrict__ br_l,
    const float* __restrict__ h0,
    const float* __restrict__ gM0,  const float* __restrict__ gM1,
    float* __restrict__ F)
{
    int tid = threadIdx.x;
    int cnt = g_cnt;
    int e0 = (blockIdx.x*4 + (tid>>5))*8;
    if(e0 >= cnt) return;
    int lane = tid & 31;
    int c = 2*lane;
    int eend = min(e0 + 8, cnt);

    float2 WA[NBF], WB[NBF];
    const float2* wa = (const float2*)Wr_l;
    const float2* wb = (const float2*)Wr_l + 512;    // path 1
#pragma unroll
    for(int b=0;b<NBF;b++){ WA[b] = wa[b*32+lane]; WB[b] = wb[b*32+lane]; }
    float2 bA = ((const float2*)br_l)[lane];
    float2 bB = ((const float2*)br_l)[32+lane];

    int curi = g_Iij[e0].x;
    float2 gm0 = *(const float2*)&gM0[curi*64+c];
    float2 gm1[3];
#pragma unroll
    for(int x=0;x<3;x++) gm1[x] = *(const float2*)&gM1[(curi*3+x)*64+c];
    float fi = 0.f;

    for(int e=e0;e<eend;e++){
        int2 ij = g_Iij[e];
        if(ij.x != curi){
            if(lane < 3) atomicAdd(&F[curi*3+lane], fi);
            fi = 0.f;
            curi = ij.x;
            gm0 = *(const float2*)&gM0[curi*64+c];
#pragma unroll
            for(int x=0;x<3;x++) gm1[x] = *(const float2*)&gM1[(curi*3+x)*64+c];
        }
        int j = ij.y;
        float4 m = g_Im[e];
        float d = m.x;
        float rh[3] = {m.y, m.z, m.w};
        float fc = 0.5f*(__cosf(PI_F*d/RCUT) + 1.0f);
        float rb = 0.f, wbv = 0.f;
        if(lane < NBF){
            float zz = (d - lane*CSP)/WIDTH;
            rb = __expf(-zz*zz);
            wbv = rb * (-2.0f*zz/WIDTH);
        }
        float2 preA = bA, preB = bB;
        float2 qA = make_float2(0,0), qB = make_float2(0,0);
#pragma unroll
        for(int b=0;b<NBF;b++){
            float r = __shfl_sync(FULLMASK, rb, b);
            float w = __shfl_sync(FULLMASK, wbv, b);
            preA.x = fmaf(r, WA[b].x, preA.x); preA.y = fmaf(r, WA[b].y, preA.y);
            preB.x = fmaf(r, WB[b].x, preB.x); preB.y = fmaf(r, WB[b].y, preB.y);
            qA.x = fmaf(w, WA[b].x, qA.x); qA.y = fmaf(w, WA[b].y, qA.y);
            qB.x = fmaf(w, WB[b].x, qB.x); qB.y = fmaf(w, WB[b].y, qB.y);
        }
        float2 h0j = *(const float2*)&h0[j*64+c];
        float gmrx = gm1[0].x*rh[0] + gm1[1].x*rh[1] + gm1[2].x*rh[2];
        float gmry = gm1[0].y*rh[0] + gm1[1].y*rh[1] + gm1[2].y*rh[2];

        float gf0x = gm0.x*h0j.x, gf0y = gm0.y*h0j.y;
        float gf1x = gmrx*h0j.x,  gf1y = gmry*h0j.y;
        float sfc = gf0x*preA.x + gf0y*preA.y + gf1x*preB.x + gf1y*preB.y;
        float sd  = gf0x*qA.x   + gf0y*qA.y   + gf1x*qB.x   + gf1y*qB.y;
        float f1x = fc*preB.x*h0j.x, f1y = fc*preB.y*h0j.y;
        float gr0 = gm1[0].x*f1x + gm1[0].y*f1y;
        float gr1 = gm1[1].x*f1x + gm1[1].y*f1y;
        float gr2 = gm1[2].x*f1x + gm1[2].y*f1y;

        sfc = warpRed(sfc);
        sd  = warpRed(sd);
        gr0 = warpRed(gr0);
        gr1 = warpRed(gr1);
        gr2 = warpRed(gr2);

        float dfc = -0.5f*(PI_F/RCUT)*__sinf(PI_F*d/RCUT);
        float gd  = fc*sd + sfc*dfc;
        float gdr = gr0*rh[0] + gr1*rh[1] + gr2*rh[2];
        float invd = 1.0f/d;
        if(lane < 3){
            float gx = (lane==0) ? gr0 : ((lane==1) ? gr1 : gr2);
            float rx = rh[lane];
            float grij = (gx - gdr*rx)*invd + gd*rx;
            fi += grij;
            atomicAdd(&F[j*3+lane], -grij);
        }
    }
    if(lane < 3) atomicAdd(&F[curi*3+lane], fi);
}

// ---------------- backward layer-1 (j-sorted; paths {0,2}) -----------------
__global__ __launch_bounds__(128) void edge_bwd1_k(
    const float* __restrict__ Wr_l, const float* __restrict__ br_l,
    const float* __restrict__ h0,   const float* __restrict__ h1,
    const float* __restrict__ gM0,
    float* __restrict__ gh0, float* __restrict__ gh1, float* __restrict__ F)
{
    int tid = threadIdx.x;
    int cnt = g_cnt;
    int e0 = (blockIdx.x*4 + (tid>>5))*8;
    if(e0 >= cnt) return;
    int lane = tid & 31;
    int c = 2*lane;
    int eend = min(e0 + 8, cnt);

    float2 WA[NBF], WB[NBF];
    const float2* wa = (const float2*)Wr_l;
    const float2* wb = (const float2*)Wr_l + 1024;   // path 2
#pragma unroll
    for(int b=0;b<NBF;b++){ WA[b] = wa[b*32+lane]; WB[b] = wb[b*32+lane]; }
    float2 bA = ((const float2*)br_l)[lane];
    float2 bB = ((const float2*)br_l)[64+lane];

    int curj = g_Jij[e0].y;
    float2 h0j = *(const float2*)&h0[curj*64+c];
    float2 v[3];
#pragma unroll
    for(int x=0;x<3;x++) v[x] = *(const float2*)&h1[(curj*3+x)*64+c];
    float2 acc0 = make_float2(0,0);
    float2 acc1[3] = {{0,0},{0,0},{0,0}};
    float fj = 0.f;

    for(int e=e0;e<eend;e++){
        int2 ij = g_Jij[e];
        if(ij.y != curj){
            red2(&gh0[curj*64+c], acc0.x, acc0.y);
#pragma unroll
            for(int x=0;x<3;x++) red2(&gh1[(curj*3+x)*64+c], acc1[x].x, acc1[x].y);
            if(lane < 3) atomicAdd(&F[curj*3+lane], fj);
            acc0 = make_float2(0,0);
#pragma unroll
            for(int x=0;x<3;x++) acc1[x] = make_float2(0,0);
            fj = 0.f;
            curj = ij.y;
            h0j = *(const float2*)&h0[curj*64+c];
#pragma unroll
            for(int x=0;x<3;x++) v[x] = *(const float2*)&h1[(curj*3+x)*64+c];
        }
        int i = ij.x;
        float4 m = g_Jm[e];
        float d = m.x;
        float rh[3] = {m.y, m.z, m.w};
        float fc = 0.5f*(__cosf(PI_F*d/RCUT) + 1.0f);
        float rb = 0.f, wbv = 0.f;
        if(lane < NBF){
            float zz = (d - lane*CSP)/WIDTH;
            rb = __expf(-zz*zz);
            wbv = rb * (-2.0f*zz/WIDTH);
        }
        float2 preA = bA, preB = bB;
        float2 qA = make_float2(0,0), qB = make_float2(0,0);
#pragma unroll
        for(int b=0;b<NBF;b++){
            float r = __shfl_sync(FULLMASK, rb, b);
            float w = __shfl_sync(FULLMASK, wbv, b);
            preA.x = fmaf(r, WA[b].x, preA.x); preA.y = fmaf(r, WA[b].y, preA.y);
            preB.x = fmaf(r, WB[b].x, preB.x); preB.y = fmaf(r, WB[b].y, preB.y);
            qA.x = fmaf(w, WA[b].x, qA.x); qA.y = fmaf(w, WA[b].y, qA.y);
            qB.x = fmaf(w, WB[b].x, qB.x); qB.y = fmaf(w, WB[b].y, qB.y);
        }
        float2 gm0 = *(const float2*)&gM0[i*64+c];
        float tx = v[0].x*rh[0] + v[1].x*rh[1] + v[2].x*rh[2];
        float ty = v[0].y*rh[0] + v[1].y*rh[1] + v[2].y*rh[2];

        float gf0x = gm0.x*h0j.x, gf0y = gm0.y*h0j.y;
        float gf2x = gm0.x*tx,    gf2y = gm0.y*ty;
        float sfc = gf0x*preA.x + gf0y*preA.y + gf2x*preB.x + gf2y*preB.y;
        float sd  = gf0x*qA.x   + gf0y*qA.y   + gf2x*qB.x   + gf2y*qB.y;
        float f2x = fc*preB.x*gm0.x, f2y = fc*preB.y*gm0.y;
        float gr0 = f2x*v[0].x + f2y*v[0].y;
        float gr1 = f2x*v[1].x + f2y*v[1].y;
        float gr2 = f2x*v[2].x + f2y*v[2].y;

        acc0.x += gm0.x*fc*preA.x;
        acc0.y += gm0.y*fc*preA.y;
#pragma unroll
        for(int x=0;x<3;x++){
            acc1[x].x += f2x*rh[x];
            acc1[x].y += f2y*rh[x];
        }

        sfc = warpRed(sfc);
        sd  = warpRed(sd);
        gr0 = warpRed(gr0);
        gr1 = warpRed(gr1);
        gr2 = warpRed(gr2);

        float dfc = -0.5f*(PI_F/RCUT)*__sinf(PI_F*d/RCUT);
        float gd  = fc*sd + sfc*dfc;
        float gdr = gr0*rh[0] + gr1*rh[1] + gr2*rh[2];
        float invd = 1.0f/d;
        if(lane < 3){
            float gx = (lane==0) ? gr0 : ((lane==1) ? gr1 : gr2);
            float rx = rh[lane];
            float grij = (gx - gdr*rx)*invd + gd*rx;
            atomicAdd(&F[i*3+lane], grij);
            fj -= grij;
        }
    }
    red2(&gh0[curj*64+c], acc0.x, acc0.y);
#pragma unroll
    for(int x=0;x<3;x++) red2(&gh1[(curj*3+x)*64+c], acc1[x].x, acc1[x].y);
    if(lane < 3) atomicAdd(&F[curj*3+lane], fj);
}

// ---------------- node GEMM: out = epilogue(A@W1 [+ B@W2] [+ bias]) --------
// 128 rows/block, 256 threads, 8x4 register tile.
__global__ __launch_bounds__(256) void mm_fwd(
    const float* __restrict__ A, const float* __restrict__ W1,
    const float* __restrict__ B, const float* __restrict__ W2,
    const float* __restrict__ bias, const float* __restrict__ ro2,
    float* __restrict__ out, float* __restrict__ sOut, int rows)
{
    __shared__ float sW[64*64];
    __shared__ float sX[128*64];
    int tid = threadIdx.x;
    int row0 = blockIdx.x*128;
    int tc = tid & 15, tr = tid >> 4;
    float acc[8][4];
    if(bias){
        float4 b = *(const float4*)&bias[4*tc];
#pragma unroll
        for(int i=0;i<8;i++){ acc[i][0]=b.x; acc[i][1]=b.y; acc[i][2]=b.z; acc[i][3]=b.w; }
    } else {
#pragma unroll
        for(int i=0;i<8;i++){ acc[i][0]=acc[i][1]=acc[i][2]=acc[i][3]=0.f; }
    }
    int nph = B ? 2 : 1;
    for(int ph=0; ph<nph; ph++){
        const float* Xp = ph ? B : A;
        const float* Wp = ph ? W2 : W1;
        if(ph) __syncthreads();
        for(int k=tid;k<4096;k+=256) sW[k] = Wp[k];
        for(int k=tid;k<8192;k+=256){
            int r = k>>6, c = k&63;
            int gr = row0 + r;
            sX[k] = (gr < rows) ? Xp[gr*64+c] : 0.f;
        }
        __syncthreads();
        const float* xr = &sX[(tr*8)*64];
#pragma unroll 4
        for(int k=0;k<64;k++){
            float4 w = *(const float4*)&sW[k*64 + tc*4];
            float a[8];
#pragma unroll
            for(int i=0;i<8;i++) a[i] = xr[i*64+k];
#pragma unroll
            for(int i=0;i<8;i++){
                acc[i][0]=fmaf(a[i],w.x,acc[i][0]);
                acc[i][1]=fmaf(a[i],w.y,acc[i][1]);
                acc[i][2]=fmaf(a[i],w.z,acc[i][2]);
                acc[i][3]=fmaf(a[i],w.w,acc[i][3]);
            }
        }
    }
    float4 ro2v = make_float4(0,0,0,0);
    if(ro2) ro2v = *(const float4*)&ro2[4*tc];
#pragma unroll
    for(int i=0;i<8;i++){
        int r = row0 + tr*8 + i;
        if(r >= rows) continue;
        float4 o;
        float* oo = &o.x;
#pragma unroll
        for(int jj=0;jj<4;jj++){
            float u = acc[i][jj];
            float val;
            if(ro2){
                float sig = 1.f/(1.f + expf(-u));
                float rr = (&ro2v.x)[jj];
                val = rr*sig*fmaf(u, 1.f-sig, 1.f);
            } else if(sOut){
                float sig = 1.f/(1.f + expf(-u));
                val = u*sig;
            } else {
                val = u;
            }
            oo[jj] = val;
        }
        if(sOut){
            float4 so = make_float4(acc[i][0],acc[i][1],acc[i][2],acc[i][3]);
            *(float4*)&sOut[r*64 + tc*4] = so;
        }
        *(float4*)&out[r*64 + tc*4] = o;
    }
}

// ---------------- node GEMM transposed with fused dsilu --------------------
__global__ __launch_bounds__(256) void mm_bwdT(
    const float* __restrict__ G, const float* __restrict__ S,
    const float* __restrict__ W1, const float* __restrict__ W2,
    float* __restrict__ out1, float* __restrict__ out2, int rows)
{
    __shared__ float sWt[64*68];
    __shared__ float sG[64*65];
    int tid = threadIdx.x;
    int row0 = blockIdx.x*64;
    int tc = tid & 15, tr = tid >> 4;
    for(int k=tid;k<4096;k+=256){
        int r = k>>6, c = k&63;
        int gr = row0 + r;
        float v = 0.f;
        if(gr < rows){
            float g = G[gr*64+c];
            if(S){
                float x = S[gr*64+c];
                float sig = 1.f/(1.f + expf(-x));
                v = g*sig*fmaf(x, 1.f-sig, 1.f);
            } else v = g;
        }
        sG[r*65+c] = v;
    }
    int nph = out2 ? 2 : 1;
    for(int ph=0; ph<nph; ph++){
        const float* Wp = ph ? W2 : W1;
        float* op = ph ? out2 : out1;
        if(ph) __syncthreads();
        for(int k=tid;k<4096;k+=256){
            int cout = k>>6, dd = k&63;
            sWt[dd*68+cout] = Wp[k];
        }
        __syncthreads();
        float acc[4][4];
#pragma unroll
        for(int i=0;i<4;i++){ acc[i][0]=acc[i][1]=acc[i][2]=acc[i][3]=0.f; }
        const float* xr = &sG[(tr*4)*65];
#pragma unroll 8
        for(int k=0;k<64;k++){
            float a0 = xr[k], a1 = xr[65+k], a2 = xr[130+k], a3 = xr[195+k];
            float4 w = *(const float4*)&sWt[k*68 + tc*4];
            acc[0][0]=fmaf(a0,w.x,acc[0][0]); acc[0][1]=fmaf(a0,w.y,acc[0][1]);
            acc[0][2]=fmaf(a0,w.z,acc[0][2]); acc[0][3]=fmaf(a0,w.w,acc[0][3]);
            acc[1][0]=fmaf(a1,w.x,acc[1][0]); acc[1][1]=fmaf(a1,w.y,acc[1][1]);
            acc[1][2]=fmaf(a1,w.z,acc[1][2]); acc[1][3]=fmaf(a1,w.w,acc[1][3]);
            acc[2][0]=fmaf(a2,w.x,acc[2][0]); acc[2][1]=fmaf(a2,w.y,acc[2][1]);
            acc[2][2]=fmaf(a2,w.z,acc[2][2]); acc[2][3]=fmaf(a2,w.w,acc[2][3]);
            acc[3][0]=fmaf(a3,w.x,acc[3][0]); acc[3][1]=fmaf(a3,w.y,acc[3][1]);
            acc[3][2]=fmaf(a3,w.z,acc[3][2]); acc[3][3]=fmaf(a3,w.w,acc[3][3]);
        }
#pragma unroll
        for(int i=0;i<4;i++){
            int r = row0 + tr*4 + i;
            if(r >= rows) continue;
            float4 o = make_float4(acc[i][0],acc[i][1],acc[i][2],acc[i][3]);
            *(float4*)&op[r*64 + tc*4] = o;
        }
    }
}

// ---------------- fused readout backward -----------------------------------
__global__ __launch_bounds__(256) void readout_k(
    const float* __restrict__ A, const float* __restrict__ Wro1,
    const float* __restrict__ bro1, const float* __restrict__ Wro2,
    float* __restrict__ gA, int rows)
{
    __shared__ float sW[64*68];
    __shared__ float sX[64*65];
    int tid = threadIdx.x;
    int row0 = blockIdx.x*64;
    int tc = tid & 15, tr = tid >> 4;
    for(int k=tid;k<4096;k+=256) sW[k] = Wro1[k];
    for(int k=tid;k<4096;k+=256){
        int r = k>>6, c = k&63;
        int gr = row0 + r;
        sX[r*65+c] = (gr < rows) ? A[gr*64+c] : 0.f;
    }
    __syncthreads();
    float acc[4][4];
    {
        float4 b = *(const float4*)&bro1[4*tc];
#pragma unroll
        for(int i=0;i<4;i++){ acc[i][0]=b.x; acc[i][1]=b.y; acc[i][2]=b.z; acc[i][3]=b.w; }
    }
    {
        const float* xr = &sX[(tr*4)*65];
#pragma unroll 8
        for(int k=0;k<64;k++){
            float a0 = xr[k], a1 = xr[65+k], a2 = xr[130+k], a3 = xr[195+k];
            float4 w = *(const float4*)&sW[k*64 + tc*4];
            acc[0][0]=fmaf(a0,w.x,acc[0][0]); acc[0][1]=fmaf(a0,w.y,acc[0][1]);
            acc[0][2]=fmaf(a0,w.z,acc[0][2]); acc[0][3]=fmaf(a0,w.w,acc[0][3]);
            acc[1][0]=fmaf(a1,w.x,acc[1][0]); acc[1][1]=fmaf(a1,w.y,acc[1][1]);
            acc[1][2]=fmaf(a1,w.z,acc[1][2]); acc[1][3]=fmaf(a1,w.w,acc[1][3]);
            acc[2][0]=fmaf(a2,w.x,acc[2][0]); acc[2][1]=fmaf(a2,w.y,acc[2][1]);
            acc[2][2]=fmaf(a2,w.z,acc[2][2]); acc[2][3]=fmaf(a2,w.w,acc[2][3]);
            acc[3][0]=fmaf(a3,w.x,acc[3][0]); acc[3][1]=fmaf(a3,w.y,acc[3][1]);
            acc[3][2]=fmaf(a3,w.z,acc[3][2]); acc[3][3]=fmaf(a3,w.w,acc[3][3]);
        }
    }
    __syncthreads();
    {
        float4 ro2v = *(const float4*)&Wro2[4*tc];
#pragma unroll
        for(int i=0;i<4;i++){
#pragma unroll
            for(int jj=0;jj<4;jj++){
                float u = acc[i][jj];
                float sig = 1.f/(1.f + expf(-u));
                float w = (&ro2v.x)[jj]*sig*fmaf(u, 1.f-sig, 1.f);
                sX[(tr*4+i)*65 + tc*4 + jj] = w;
            }
        }
    }
    for(int k=tid;k<4096;k+=256){
        int cout = k>>6, dd = k&63;
        sW[dd*68+cout] = Wro1[k];
    }
    __syncthreads();
    float acc2[4][4];
#pragma unroll
    for(int i=0;i<4;i++){ acc2[i][0]=acc2[i][1]=acc2[i][2]=acc2[i][3]=0.f; }
    {
        const float* xr = &sX[(tr*4)*65];
#pragma unroll 8
        for(int k=0;k<64;k++){
            float a0 = xr[k], a1 = xr[65+k], a2 = xr[130+k], a3 = xr[195+k];
            float4 w = *(const float4*)&sW[k*68 + tc*4];
            acc2[0][0]=fmaf(a0,w.x,acc2[0][0]); acc2[0][1]=fmaf(a0,w.y,acc2[0][1]);
            acc2[0][2]=fmaf(a0,w.z,acc2[0][2]); acc2[0][3]=fmaf(a0,w.w,acc2[0][3]);
            acc2[1][0]=fmaf(a1,w.x,acc2[1][0]); acc2[1][1]=fmaf(a1,w.y,acc2[1][1]);
            acc2[1][2]=fmaf(a1,w.z,acc2[1][2]); acc2[1][3]=fmaf(a1,w.w,acc2[1][3]);
            acc2[2][0]=fmaf(a2,w.x,acc2[2][0]); acc2[2][1]=fmaf(a2,w.y,acc2[2][1]);
            acc2[2][2]=fmaf(a2,w.z,acc2[2][2]); acc2[2][3]=fmaf(a2,w.w,acc2[2][3]);
            acc2[3][0]=fmaf(a3,w.x,acc2[3][0]); acc2[3][1]=fmaf(a3,w.y,acc2[3][1]);
            acc2[3][2]=fmaf(a3,w.z,acc2[3][2]); acc2[3][3]=fmaf(a3,w.w,acc2[3][3]);
        }
    }
#pragma unroll
    for(int i=0;i<4;i++){
        int r = row0 + tr*4 + i;
        if(r >= rows) continue;
        float4 o = make_float4(acc2[i][0],acc2[i][1],acc2[i][2],acc2[i][3]);
        *(float4*)&gA[r*64 + tc*4] = o;
    }
}

// ---------------- host orchestration ---------------------------------------
extern "C" void kernel_launch(void* const* d_in, const int* in_sizes, int n_in,
                              void* d_out, int out_size)
{
    const float* coord  = (const float*)d_in[0];
    const float* emb    = (const float*)d_in[1];
    const float* Wr     = (const float*)d_in[2];
    const float* br     = (const float*)d_in[3];
    const float* Wself0 = (const float*)d_in[4];
    const float* Wmsg0  = (const float*)d_in[5];
    const float* b0     = (const float*)d_in[6];
    const float* Wmsg1  = (const float*)d_in[7];
    const float* Wro1   = (const float*)d_in[9];
    const float* bro1   = (const float*)d_in[10];
    const float* Wro2   = (const float*)d_in[11];
    const int*   z      = (const int*)d_in[13];
    const int*   ei     = (const int*)d_in[14];
    const int*   ej     = (const int*)d_in[15];
    float* F = (float*)d_out;
    (void)in_sizes; (void)n_in; (void)out_size;

    void *phist;
    float *h0a,*h0b,*h0c,*s0,*s1,*h1b,*Mbuf,*gM0p,*gM1p,*gA,*gB,*gh1;
    cudaGetSymbolAddress(&phist, g_hist);
    cudaGetSymbolAddress((void**)&h0a, g_h0a);
    cudaGetSymbolAddress((void**)&h0b, g_h0b);
    cudaGetSymbolAddress((void**)&h0c, g_h0c);
    cudaGetSymbolAddress((void**)&s0,  g_s0);
    cudaGetSymbolAddress((void**)&s1,  g_s1);
    cudaGetSymbolAddress((void**)&h1b, g_h1b);
    cudaGetSymbolAddress((void**)&Mbuf,g_M);
    cudaGetSymbolAddress((void**)&gM0p,g_gM0);
    cudaGetSymbolAddress((void**)&gM1p,g_gM1);
    cudaGetSymbolAddress((void**)&gA,  g_gA);
    cudaGetSymbolAddress((void**)&gB,  g_gB);
    cudaGetSymbolAddress((void**)&gh1, g_gh1);
    float* M0 = Mbuf;
    float* M1 = Mbuf + NN*CC;

    const int EB  = (EE + 31)/32;       // 4 warps x 8 edges per 128-thread block
    const int G1  = (NN + 127)/128;
    const int G3  = (3*NN + 127)/128;
    const int T1  = (NN + 63)/64;
    const int T3  = (3*NN + 63)/64;

    cudaMemsetAsync(phist, 0, 2*NN*sizeof(int));
    cudaMemsetAsync(F, 0, NN*3*sizeof(float));
    geomA_k<<<(EE+255)/256, 256>>>(coord, ei, ej);
    scan_k<<<1, 1024>>>();
    geomB_k<<<(EE+255)/256, 256>>>(coord, ei, ej);
    embed_k<<<320, 256>>>(emb, z);

    // ---- layer 0 forward
    cudaMemsetAsync(Mbuf, 0, NN*CC*4*sizeof(float));
    edge_fwd0_k<<<EB, 128>>>(Wr, br, h0a);
    mm_fwd<<<G1, 256>>>(M0, Wmsg0, h0a, Wself0, b0, nullptr, h0b, s0, NN);
    mm_fwd<<<G3, 256>>>(M1, Wmsg1, nullptr, nullptr, nullptr, nullptr, h1b, nullptr, 3*NN);

    // ---- layer 1 forward (M1/h1 outputs dead)
    cudaMemsetAsync(M0, 0, NN*CC*sizeof(float));
    edge_fwd1_k<<<EB, 128>>>(Wr + 4096, br + 256, h0b, h1b);
    mm_fwd<<<G1, 256>>>(M0, Wmsg0 + 4096, h0b, Wself0 + 4096, b0 + 64, nullptr, h0c, s1, NN);

    // ---- readout backward (fused)
    readout_k<<<T1, 256>>>(h0c, Wro1, bro1, Wro2, gA, NN);

    // ---- layer 1 backward (j-sorted scatter)
    mm_bwdT<<<T1, 256>>>(gA, s1, Wmsg0 + 4096, Wself0 + 4096, gM0p, gB, NN);
    cudaMemsetAsync(gh1, 0, NN*3*CC*sizeof(float));
    edge_bwd1_k<<<EB, 128>>>(Wr + 4096, br + 256, h0b, h1b, gM0p, gB, gh1, F);

    // ---- layer 0 backward (i-sorted)
    mm_bwdT<<<T1, 256>>>(gB, s0, Wmsg0, nullptr, gM0p, nullptr, NN);
    mm_bwdT<<<T3, 256>>>(gh1, nullptr, Wmsg1, nullptr, gM1p, nullptr, 3*NN);
    edge_bwd0_k<<<EB, 128>>>(Wr, br, h0a, gM0p, gM1p, F);
}